// round 2
// baseline (speedup 1.0000x reference)
#include <cuda_runtime.h>

#define N_ROWS 6400
#define DIMV 64
#define NUM_EMB 512
#define GROUP 100

// ---- scratch (no cudaMalloc allowed) ----
__device__ float g_qis[N_ROWS * DIMV];
__device__ float g_kis[N_ROWS * DIMV];
__device__ float g_vis[N_ROWS * DIMV];
__device__ float g_qcs[N_ROWS * DIMV];
__device__ float g_kcs[N_ROWS * DIMV];
__device__ float g_vcs[N_ROWS * DIMV];

// ============================================================
// Kernel A: six fused projections  out = x @ W + b
// grid 100 x 256 threads, 64 rows per CTA
// ============================================================
__global__ __launch_bounds__(256) void proj_kernel(
    const float* __restrict__ x,
    const float* __restrict__ W0, const float* __restrict__ b0,
    const float* __restrict__ W1, const float* __restrict__ b1,
    const float* __restrict__ W2, const float* __restrict__ b2,
    const float* __restrict__ W3, const float* __restrict__ b3,
    const float* __restrict__ W4, const float* __restrict__ b4,
    const float* __restrict__ W5, const float* __restrict__ b5)
{
    __shared__ float xs[64 * 64];
    __shared__ float Ws[64 * 64];
    __shared__ float bs[64];
    int rowBase = blockIdx.x * 64;
    for (int i = threadIdx.x; i < 64 * 64; i += 256)
        xs[i] = x[rowBase * 64 + i];

    const float* Wl[6] = {W0, W1, W2, W3, W4, W5};
    const float* bl[6] = {b0, b1, b2, b3, b4, b5};
    float* ol[6] = {g_qis, g_kis, g_vis, g_qcs, g_kcs, g_vcs};

    int w = threadIdx.x >> 5, lane = threadIdx.x & 31;
    for (int p = 0; p < 6; p++) {
        __syncthreads();
        for (int i = threadIdx.x; i < 64 * 64; i += 256) Ws[i] = Wl[p][i];
        if (threadIdx.x < 64) bs[threadIdx.x] = bl[p][threadIdx.x];
        __syncthreads();

        float a0[8], a1[8];
#pragma unroll
        for (int r = 0; r < 8; r++) { a0[r] = 0.f; a1[r] = 0.f; }
        for (int d = 0; d < 64; d++) {
            float w0 = Ws[d * 64 + lane];
            float w1 = Ws[d * 64 + lane + 32];
#pragma unroll
            for (int r = 0; r < 8; r++) {
                float xv = xs[(8 * w + r) * 64 + d];
                a0[r] = fmaf(xv, w0, a0[r]);
                a1[r] = fmaf(xv, w1, a1[r]);
            }
        }
        float bb0 = bs[lane], bb1 = bs[lane + 32];
        float* o = ol[p];
#pragma unroll
        for (int r = 0; r < 8; r++) {
            int row = rowBase + 8 * w + r;
            o[row * 64 + lane]      = a0[r] + bb0;
            o[row * 64 + lane + 32] = a1[r] + bb1;
        }
    }
}

// ============================================================
// Kernel B: vector quantization (argmin over 512 codes) + gather
// grid 200 x 256, 32 rows per CTA, codebook in 8 chunks of 64
// ============================================================
__global__ __launch_bounds__(256) void quant_kernel(
    const float* __restrict__ x, const float* __restrict__ cb,
    float* __restrict__ outQ)
{
    __shared__ float fs[32 * 68];
    __shared__ float cs[64 * 68];
    int rowBase = blockIdx.x * 32;
    for (int i = threadIdx.x; i < 32 * 64; i += 256)
        fs[(i >> 6) * 68 + (i & 63)] = x[rowBase * 64 + i];

    int w = threadIdx.x >> 5, lane = threadIdx.x & 31;
    float bestd[4]; int besti[4];
#pragma unroll
    for (int r = 0; r < 4; r++) { bestd[r] = 3.4e38f; besti[r] = 0; }

    const float4* fs4 = (const float4*)fs;
    const float4* cs4 = (const float4*)cs;

    for (int ch = 0; ch < 8; ch++) {
        __syncthreads();
        for (int i = threadIdx.x; i < 64 * 64; i += 256)
            cs[(i >> 6) * 68 + (i & 63)] = cb[ch * 64 * 64 + i];
        __syncthreads();

        float d0[4], d1[4];
#pragma unroll
        for (int r = 0; r < 4; r++) { d0[r] = 0.f; d1[r] = 0.f; }
#pragma unroll 4
        for (int q = 0; q < 16; q++) {
            float4 c0 = cs4[lane * 17 + q];
            float4 c1 = cs4[(lane + 32) * 17 + q];
#pragma unroll
            for (int r = 0; r < 4; r++) {
                float4 f = fs4[(4 * w + r) * 17 + q];
                float t;
                t = f.x - c0.x; d0[r] = fmaf(t, t, d0[r]);
                t = f.y - c0.y; d0[r] = fmaf(t, t, d0[r]);
                t = f.z - c0.z; d0[r] = fmaf(t, t, d0[r]);
                t = f.w - c0.w; d0[r] = fmaf(t, t, d0[r]);
                t = f.x - c1.x; d1[r] = fmaf(t, t, d1[r]);
                t = f.y - c1.y; d1[r] = fmaf(t, t, d1[r]);
                t = f.z - c1.z; d1[r] = fmaf(t, t, d1[r]);
                t = f.w - c1.w; d1[r] = fmaf(t, t, d1[r]);
            }
        }
#pragma unroll
        for (int r = 0; r < 4; r++) {
            int i0 = ch * 64 + lane;
            if (d0[r] < bestd[r]) { bestd[r] = d0[r]; besti[r] = i0; }
            if (d1[r] < bestd[r]) { bestd[r] = d1[r]; besti[r] = i0 + 32; }
        }
    }
#pragma unroll
    for (int r = 0; r < 4; r++) {
#pragma unroll
        for (int off = 16; off > 0; off >>= 1) {
            float ob = __shfl_xor_sync(0xffffffffu, bestd[r], off);
            int   oi = __shfl_xor_sync(0xffffffffu, besti[r], off);
            if (ob < bestd[r] || (ob == bestd[r] && oi < besti[r])) {
                bestd[r] = ob; besti[r] = oi;
            }
        }
        int idx = besti[r];
        int row = rowBase + 4 * w + r;
        outQ[row * 64 + lane]      = cb[idx * 64 + lane];
        outQ[row * 64 + lane + 32] = cb[idx * 64 + lane + 32];
    }
}

// ============================================================
// Kernel C: intra-sample attention. One CTA per (b,d), 50x50, dim 64.
// scores[s][t] = k[s] . q[t], softmax over t, Z = P @ V
// ============================================================
__global__ __launch_bounds__(256) void is_attn_kernel(float* __restrict__ outZ)
{
    __shared__ float qs[64 * 68];   // padded rows; rows 50..63 uninitialized (masked)
    __shared__ float ks[50 * 64];
    __shared__ float vs[50 * 64];
    __shared__ float pbuf[8 * 64];

    int base = blockIdx.x * 50;
    for (int i = threadIdx.x; i < 50 * 64; i += 256) {
        int r = i >> 6, c = i & 63;
        qs[r * 68 + c] = g_qis[base * 64 + i];
        ks[i] = g_kis[base * 64 + i];
        vs[i] = g_vis[base * 64 + i];
    }
    __syncthreads();

    int w = threadIdx.x >> 5, lane = threadIdx.x & 31;
    const float4* qs4 = (const float4*)qs;
    const float4* ks4 = (const float4*)ks;

    for (int s = w; s < 50; s += 8) {
        int t1 = lane + 32;
        float a0 = 0.f, a1 = 0.f;
#pragma unroll 4
        for (int q = 0; q < 16; q++) {
            float4 kv = ks4[s * 16 + q];
            float4 q0 = qs4[lane * 17 + q];
            float4 q1 = qs4[t1 * 17 + q];
            a0 = fmaf(kv.x, q0.x, a0); a0 = fmaf(kv.y, q0.y, a0);
            a0 = fmaf(kv.z, q0.z, a0); a0 = fmaf(kv.w, q0.w, a0);
            a1 = fmaf(kv.x, q1.x, a1); a1 = fmaf(kv.y, q1.y, a1);
            a1 = fmaf(kv.z, q1.z, a1); a1 = fmaf(kv.w, q1.w, a1);
        }
        float s0 = a0;
        float s1 = (t1 < 50) ? a1 : -1e30f;
        float m = fmaxf(s0, s1);
#pragma unroll
        for (int off = 16; off > 0; off >>= 1)
            m = fmaxf(m, __shfl_xor_sync(0xffffffffu, m, off));
        float p0 = __expf(s0 - m);
        float p1 = (t1 < 50) ? __expf(s1 - m) : 0.f;
        float ls = p0 + p1;
#pragma unroll
        for (int off = 16; off > 0; off >>= 1)
            ls += __shfl_xor_sync(0xffffffffu, ls, off);

        pbuf[w * 64 + lane] = p0;
        pbuf[w * 64 + t1]   = p1;
        __syncwarp();

        float z0 = 0.f, z1 = 0.f;
#pragma unroll 5
        for (int t = 0; t < 50; t++) {
            float p = pbuf[w * 64 + t];
            z0 = fmaf(p, vs[t * 64 + lane], z0);
            z1 = fmaf(p, vs[t * 64 + lane + 32], z1);
        }
        float inv = 1.f / ls;
        outZ[(base + s) * 64 + lane]      = z0 * inv;
        outZ[(base + s) * 64 + lane + 32] = z1 * inv;
        __syncwarp();
    }
}

// ============================================================
// Kernel D: cross-sample attention, flash-style.
// "Q" rows = kc, "K" cols = qc, V = vc; masked where sample blocks match.
// grid 200 x 256, M=32 query rows, Ktile=64, exactly 48KB static smem.
// K tile stored with XOR-on-float4 swizzle (no padding).
// ============================================================
__global__ __launch_bounds__(256) void cs_attn_kernel(float* __restrict__ outX)
{
    __shared__ float Qs[32 * 64];
    __shared__ float Ks[64 * 64];   // swizzled
    __shared__ float Vs[64 * 64];
    __shared__ float Ps[32 * 64];

    int qBase = blockIdx.x * 32;
    for (int i = threadIdx.x; i < 32 * 64; i += 256)
        Qs[i] = g_kcs[qBase * 64 + i];

    int w = threadIdx.x >> 5, lane = threadIdx.x & 31;
    int rl = lane >> 4;            // 0/1 -> local row selector for PV
    int e4 = lane & 15;            // float4 column index for O

    float4 oLo = {0.f, 0.f, 0.f, 0.f};
    float4 oHi = {0.f, 0.f, 0.f, 0.f};
    float mrow[4], lrow[4];
#pragma unroll
    for (int r = 0; r < 4; r++) { mrow[r] = -3.4e38f; lrow[r] = 0.f; }

    int qSamp[4];
#pragma unroll
    for (int r = 0; r < 4; r++) qSamp[r] = (qBase + 4 * w + r) / GROUP;

    const float4* Qs4 = (const float4*)Qs;
    const float4* Ks4 = (const float4*)Ks;
    const float4* Vs4 = (const float4*)Vs;

    int swz0 = lane & 15;          // swizzle key for lane's two K rows

    for (int kt = 0; kt < 100; kt++) {
        __syncthreads();
        int kBase = kt * 64;
        for (int i = threadIdx.x; i < 64 * 64; i += 256) {
            int c = i >> 6, d = i & 63;
            int chunk = (d >> 2) ^ (c & 15);
            Ks[c * 64 + chunk * 4 + (d & 3)] = g_qcs[kBase * 64 + i];
            Vs[i] = g_vcs[kBase * 64 + i];
        }
        __syncthreads();

        int c0 = kBase + lane, c1 = c0 + 32;
        int s0samp = c0 / GROUP, s1samp = c1 / GROUP;

        float sv0[4], sv1[4];
#pragma unroll
        for (int r = 0; r < 4; r++) { sv0[r] = 0.f; sv1[r] = 0.f; }
#pragma unroll 4
        for (int q = 0; q < 16; q++) {
            int qs = q ^ swz0;
            float4 k0 = Ks4[lane * 16 + qs];
            float4 k1 = Ks4[(lane + 32) * 16 + qs];
#pragma unroll
            for (int r = 0; r < 4; r++) {
                float4 qq = Qs4[(4 * w + r) * 16 + q];
                sv0[r] = fmaf(qq.x, k0.x, sv0[r]); sv0[r] = fmaf(qq.y, k0.y, sv0[r]);
                sv0[r] = fmaf(qq.z, k0.z, sv0[r]); sv0[r] = fmaf(qq.w, k0.w, sv0[r]);
                sv1[r] = fmaf(qq.x, k1.x, sv1[r]); sv1[r] = fmaf(qq.y, k1.y, sv1[r]);
                sv1[r] = fmaf(qq.z, k1.z, sv1[r]); sv1[r] = fmaf(qq.w, k1.w, sv1[r]);
            }
        }

        float corr[4];
#pragma unroll
        for (int r = 0; r < 4; r++) {
            if (s0samp == qSamp[r]) sv0[r] = -1e30f;
            if (s1samp == qSamp[r]) sv1[r] = -1e30f;
            float m = fmaxf(sv0[r], sv1[r]);
#pragma unroll
            for (int off = 16; off > 0; off >>= 1)
                m = fmaxf(m, __shfl_xor_sync(0xffffffffu, m, off));
            float mnew = fmaxf(mrow[r], m);
            corr[r] = __expf(mrow[r] - mnew);
            mrow[r] = mnew;
            float p0 = __expf(sv0[r] - mnew);
            float p1 = __expf(sv1[r] - mnew);
            Ps[(4 * w + r) * 64 + lane]      = p0;
            Ps[(4 * w + r) * 64 + lane + 32] = p1;
            float ls = p0 + p1;
#pragma unroll
            for (int off = 16; off > 0; off >>= 1)
                ls += __shfl_xor_sync(0xffffffffu, ls, off);
            lrow[r] = lrow[r] * corr[r] + ls;
        }
        __syncwarp();

        float cLo = corr[rl], cHi = corr[rl + 2];
        oLo.x *= cLo; oLo.y *= cLo; oLo.z *= cLo; oLo.w *= cLo;
        oHi.x *= cHi; oHi.y *= cHi; oHi.z *= cHi; oHi.w *= cHi;

        const float* PsLo = Ps + (4 * w + rl) * 64;
        const float* PsHi = Ps + (4 * w + rl + 2) * 64;
#pragma unroll 8
        for (int c = 0; c < 64; c++) {
            float4 vv = Vs4[c * 16 + e4];
            float plo = PsLo[c], phi = PsHi[c];
            oLo.x = fmaf(plo, vv.x, oLo.x); oLo.y = fmaf(plo, vv.y, oLo.y);
            oLo.z = fmaf(plo, vv.z, oLo.z); oLo.w = fmaf(plo, vv.w, oLo.w);
            oHi.x = fmaf(phi, vv.x, oHi.x); oHi.y = fmaf(phi, vv.y, oHi.y);
            oHi.z = fmaf(phi, vv.z, oHi.z); oHi.w = fmaf(phi, vv.w, oHi.w);
        }
    }

    float invLo = 1.f / lrow[rl];
    float invHi = 1.f / lrow[rl + 2];
    int rowLo = qBase + 4 * w + rl;
    int rowHi = rowLo + 2;
    float4 a, b;
    a.x = oLo.x * invLo; a.y = oLo.y * invLo; a.z = oLo.z * invLo; a.w = oLo.w * invLo;
    b.x = oHi.x * invHi; b.y = oHi.y * invHi; b.z = oHi.z * invHi; b.w = oHi.w * invHi;
    ((float4*)outX)[rowLo * 16 + e4] = a;
    ((float4*)outX)[rowHi * 16 + e4] = b;
}

// ============================================================
extern "C" void kernel_launch(void* const* d_in, const int* in_sizes, int n_in,
                              void* d_out, int out_size)
{
    const float* x    = (const float*)d_in[0];
    const float* cb   = (const float*)d_in[1];
    const float* Wqis = (const float*)d_in[2];  const float* bqis = (const float*)d_in[3];
    const float* Wkis = (const float*)d_in[4];  const float* bkis = (const float*)d_in[5];
    const float* Wvis = (const float*)d_in[6];  const float* bvis = (const float*)d_in[7];
    const float* Wqcs = (const float*)d_in[8];  const float* bqcs = (const float*)d_in[9];
    const float* Wkcs = (const float*)d_in[10]; const float* bkcs = (const float*)d_in[11];
    const float* Wvcs = (const float*)d_in[12]; const float* bvcs = (const float*)d_in[13];
    float* out = (float*)d_out;

    proj_kernel<<<100, 256>>>(x, Wqis, bqis, Wkis, bkis, Wvis, bvis,
                                 Wqcs, bqcs, Wkcs, bkcs, Wvcs, bvcs);
    quant_kernel<<<200, 256>>>(x, cb, out);                    // quantized @ 0
    is_attn_kernel<<<128, 256>>>(out + N_ROWS * DIMV);         // Z @ 409600
    cs_attn_kernel<<<200, 256>>>(out + 2 * N_ROWS * DIMV);     // X @ 819200
}

// round 3
// speedup vs baseline: 1.3645x; 1.3645x over previous
#include <cuda_runtime.h>

#define N_ROWS 6400
#define DIMV 64
#define NUM_EMB 512
#define GROUP 100
#define NSPLIT 3
#define TILES_PER_SPLIT 34   // 34 + 34 + 32 = 100

// ---- scratch (no cudaMalloc allowed) ----
__device__ float g_qis[N_ROWS * DIMV];
__device__ float g_kis[N_ROWS * DIMV];
__device__ float g_vis[N_ROWS * DIMV];
__device__ float g_qcs[N_ROWS * DIMV];
__device__ float g_kcs[N_ROWS * DIMV];
__device__ float g_vcs[N_ROWS * DIMV];
// split-K partials for CS attention
__device__ float g_Opart[NSPLIT][N_ROWS * DIMV];
__device__ float g_mpart[NSPLIT][N_ROWS];
__device__ float g_lpart[NSPLIT][N_ROWS];

// ============================================================
// Kernel A: six fused projections  out = x @ W + b
// ============================================================
__global__ __launch_bounds__(256) void proj_kernel(
    const float* __restrict__ x,
    const float* __restrict__ W0, const float* __restrict__ b0,
    const float* __restrict__ W1, const float* __restrict__ b1,
    const float* __restrict__ W2, const float* __restrict__ b2,
    const float* __restrict__ W3, const float* __restrict__ b3,
    const float* __restrict__ W4, const float* __restrict__ b4,
    const float* __restrict__ W5, const float* __restrict__ b5)
{
    __shared__ float xs[64 * 64];
    __shared__ float Ws[64 * 64];
    __shared__ float bs[64];
    int rowBase = blockIdx.x * 64;
    for (int i = threadIdx.x; i < 64 * 64; i += 256)
        xs[i] = x[rowBase * 64 + i];

    const float* Wl[6] = {W0, W1, W2, W3, W4, W5};
    const float* bl[6] = {b0, b1, b2, b3, b4, b5};
    float* ol[6] = {g_qis, g_kis, g_vis, g_qcs, g_kcs, g_vcs};

    int w = threadIdx.x >> 5, lane = threadIdx.x & 31;
    for (int p = 0; p < 6; p++) {
        __syncthreads();
        for (int i = threadIdx.x; i < 64 * 64; i += 256) Ws[i] = Wl[p][i];
        if (threadIdx.x < 64) bs[threadIdx.x] = bl[p][threadIdx.x];
        __syncthreads();

        float a0[8], a1[8];
#pragma unroll
        for (int r = 0; r < 8; r++) { a0[r] = 0.f; a1[r] = 0.f; }
        for (int d = 0; d < 64; d++) {
            float w0 = Ws[d * 64 + lane];
            float w1 = Ws[d * 64 + lane + 32];
#pragma unroll
            for (int r = 0; r < 8; r++) {
                float xv = xs[(8 * w + r) * 64 + d];
                a0[r] = fmaf(xv, w0, a0[r]);
                a1[r] = fmaf(xv, w1, a1[r]);
            }
        }
        float bb0 = bs[lane], bb1 = bs[lane + 32];
        float* o = ol[p];
#pragma unroll
        for (int r = 0; r < 8; r++) {
            int row = rowBase + 8 * w + r;
            o[row * 64 + lane]      = a0[r] + bb0;
            o[row * 64 + lane + 32] = a1[r] + bb1;
        }
    }
}

// ============================================================
// Kernel B: vector quantization (argmin over 512 codes) + gather
// ============================================================
__global__ __launch_bounds__(256) void quant_kernel(
    const float* __restrict__ x, const float* __restrict__ cb,
    float* __restrict__ outQ)
{
    __shared__ float fs[32 * 68];
    __shared__ float cs[64 * 68];
    int rowBase = blockIdx.x * 32;
    for (int i = threadIdx.x; i < 32 * 64; i += 256)
        fs[(i >> 6) * 68 + (i & 63)] = x[rowBase * 64 + i];

    int w = threadIdx.x >> 5, lane = threadIdx.x & 31;
    float bestd[4]; int besti[4];
#pragma unroll
    for (int r = 0; r < 4; r++) { bestd[r] = 3.4e38f; besti[r] = 0; }

    const float4* fs4 = (const float4*)fs;
    const float4* cs4 = (const float4*)cs;

    for (int ch = 0; ch < 8; ch++) {
        __syncthreads();
        for (int i = threadIdx.x; i < 64 * 64; i += 256)
            cs[(i >> 6) * 68 + (i & 63)] = cb[ch * 64 * 64 + i];
        __syncthreads();

        float d0[4], d1[4];
#pragma unroll
        for (int r = 0; r < 4; r++) { d0[r] = 0.f; d1[r] = 0.f; }
#pragma unroll 4
        for (int q = 0; q < 16; q++) {
            float4 c0 = cs4[lane * 17 + q];
            float4 c1 = cs4[(lane + 32) * 17 + q];
#pragma unroll
            for (int r = 0; r < 4; r++) {
                float4 f = fs4[(4 * w + r) * 17 + q];
                float t;
                t = f.x - c0.x; d0[r] = fmaf(t, t, d0[r]);
                t = f.y - c0.y; d0[r] = fmaf(t, t, d0[r]);
                t = f.z - c0.z; d0[r] = fmaf(t, t, d0[r]);
                t = f.w - c0.w; d0[r] = fmaf(t, t, d0[r]);
                t = f.x - c1.x; d1[r] = fmaf(t, t, d1[r]);
                t = f.y - c1.y; d1[r] = fmaf(t, t, d1[r]);
                t = f.z - c1.z; d1[r] = fmaf(t, t, d1[r]);
                t = f.w - c1.w; d1[r] = fmaf(t, t, d1[r]);
            }
        }
#pragma unroll
        for (int r = 0; r < 4; r++) {
            int i0 = ch * 64 + lane;
            if (d0[r] < bestd[r]) { bestd[r] = d0[r]; besti[r] = i0; }
            if (d1[r] < bestd[r]) { bestd[r] = d1[r]; besti[r] = i0 + 32; }
        }
    }
#pragma unroll
    for (int r = 0; r < 4; r++) {
#pragma unroll
        for (int off = 16; off > 0; off >>= 1) {
            float ob = __shfl_xor_sync(0xffffffffu, bestd[r], off);
            int   oi = __shfl_xor_sync(0xffffffffu, besti[r], off);
            if (ob < bestd[r] || (ob == bestd[r] && oi < besti[r])) {
                bestd[r] = ob; besti[r] = oi;
            }
        }
        int idx = besti[r];
        int row = rowBase + 4 * w + r;
        outQ[row * 64 + lane]      = cb[idx * 64 + lane];
        outQ[row * 64 + lane + 32] = cb[idx * 64 + lane + 32];
    }
}

// ============================================================
// Kernel C: intra-sample attention. One CTA per (b,d), 50x50, dim 64.
// ============================================================
__global__ __launch_bounds__(256) void is_attn_kernel(float* __restrict__ outZ)
{
    __shared__ float qs[64 * 68];
    __shared__ float ks[50 * 64];
    __shared__ float vs[50 * 64];
    __shared__ float pbuf[8 * 64];

    int base = blockIdx.x * 50;
    for (int i = threadIdx.x; i < 50 * 64; i += 256) {
        int r = i >> 6, c = i & 63;
        qs[r * 68 + c] = g_qis[base * 64 + i];
        ks[i] = g_kis[base * 64 + i];
        vs[i] = g_vis[base * 64 + i];
    }
    __syncthreads();

    int w = threadIdx.x >> 5, lane = threadIdx.x & 31;
    const float4* qs4 = (const float4*)qs;
    const float4* ks4 = (const float4*)ks;

    for (int s = w; s < 50; s += 8) {
        int t1 = lane + 32;
        float a0 = 0.f, a1 = 0.f;
#pragma unroll 4
        for (int q = 0; q < 16; q++) {
            float4 kv = ks4[s * 16 + q];
            float4 q0 = qs4[lane * 17 + q];
            float4 q1 = qs4[t1 * 17 + q];
            a0 = fmaf(kv.x, q0.x, a0); a0 = fmaf(kv.y, q0.y, a0);
            a0 = fmaf(kv.z, q0.z, a0); a0 = fmaf(kv.w, q0.w, a0);
            a1 = fmaf(kv.x, q1.x, a1); a1 = fmaf(kv.y, q1.y, a1);
            a1 = fmaf(kv.z, q1.z, a1); a1 = fmaf(kv.w, q1.w, a1);
        }
        float s0 = a0;
        float s1 = (t1 < 50) ? a1 : -1e30f;
        float m = fmaxf(s0, s1);
#pragma unroll
        for (int off = 16; off > 0; off >>= 1)
            m = fmaxf(m, __shfl_xor_sync(0xffffffffu, m, off));
        float p0 = __expf(s0 - m);
        float p1 = (t1 < 50) ? __expf(s1 - m) : 0.f;
        float ls = p0 + p1;
#pragma unroll
        for (int off = 16; off > 0; off >>= 1)
            ls += __shfl_xor_sync(0xffffffffu, ls, off);

        pbuf[w * 64 + lane] = p0;
        pbuf[w * 64 + t1]   = p1;
        __syncwarp();

        float z0 = 0.f, z1 = 0.f;
#pragma unroll 5
        for (int t = 0; t < 50; t++) {
            float p = pbuf[w * 64 + t];
            z0 = fmaf(p, vs[t * 64 + lane], z0);
            z1 = fmaf(p, vs[t * 64 + lane + 32], z1);
        }
        float inv = 1.f / ls;
        outZ[(base + s) * 64 + lane]      = z0 * inv;
        outZ[(base + s) * 64 + lane + 32] = z1 * inv;
        __syncwarp();
    }
}

// ============================================================
// Kernel D: cross-sample attention, flash-style with split-K.
// grid = 200 q-tiles x NSPLIT key splits. Each CTA covers up to 34
// key-tiles and emits unnormalized partial (O~, m, l).
// ============================================================
__global__ __launch_bounds__(256) void cs_attn_split_kernel()
{
    __shared__ float Qs[32 * 64];
    __shared__ float Ks[64 * 64];   // swizzled
    __shared__ float Vs[64 * 64];
    __shared__ float Ps[32 * 64];

    int qt = blockIdx.x / NSPLIT;
    int sp = blockIdx.x % NSPLIT;
    int ktStart = sp * TILES_PER_SPLIT;
    int ktEnd = ktStart + TILES_PER_SPLIT;
    if (ktEnd > 100) ktEnd = 100;

    int qBase = qt * 32;
    for (int i = threadIdx.x; i < 32 * 64; i += 256)
        Qs[i] = g_kcs[qBase * 64 + i];

    int w = threadIdx.x >> 5, lane = threadIdx.x & 31;
    int rl = lane >> 4;
    int e4 = lane & 15;

    float4 oLo = {0.f, 0.f, 0.f, 0.f};
    float4 oHi = {0.f, 0.f, 0.f, 0.f};
    float mrow[4], lrow[4];
#pragma unroll
    for (int r = 0; r < 4; r++) { mrow[r] = -3.4e38f; lrow[r] = 0.f; }

    int qSamp[4];
#pragma unroll
    for (int r = 0; r < 4; r++) qSamp[r] = (qBase + 4 * w + r) / GROUP;

    const float4* Qs4 = (const float4*)Qs;
    const float4* Ks4 = (const float4*)Ks;
    const float4* Vs4 = (const float4*)Vs;

    int swz0 = lane & 15;

    for (int kt = ktStart; kt < ktEnd; kt++) {
        __syncthreads();
        int kBase = kt * 64;
        for (int i = threadIdx.x; i < 64 * 64; i += 256) {
            int c = i >> 6, d = i & 63;
            int chunk = (d >> 2) ^ (c & 15);
            Ks[c * 64 + chunk * 4 + (d & 3)] = g_qcs[kBase * 64 + i];
            Vs[i] = g_vcs[kBase * 64 + i];
        }
        __syncthreads();

        int c0 = kBase + lane, c1 = c0 + 32;
        int s0samp = c0 / GROUP, s1samp = c1 / GROUP;

        float sv0[4], sv1[4];
#pragma unroll
        for (int r = 0; r < 4; r++) { sv0[r] = 0.f; sv1[r] = 0.f; }
#pragma unroll 4
        for (int q = 0; q < 16; q++) {
            int qs = q ^ swz0;
            float4 k0 = Ks4[lane * 16 + qs];
            float4 k1 = Ks4[(lane + 32) * 16 + qs];
#pragma unroll
            for (int r = 0; r < 4; r++) {
                float4 qq = Qs4[(4 * w + r) * 16 + q];
                sv0[r] = fmaf(qq.x, k0.x, sv0[r]); sv0[r] = fmaf(qq.y, k0.y, sv0[r]);
                sv0[r] = fmaf(qq.z, k0.z, sv0[r]); sv0[r] = fmaf(qq.w, k0.w, sv0[r]);
                sv1[r] = fmaf(qq.x, k1.x, sv1[r]); sv1[r] = fmaf(qq.y, k1.y, sv1[r]);
                sv1[r] = fmaf(qq.z, k1.z, sv1[r]); sv1[r] = fmaf(qq.w, k1.w, sv1[r]);
            }
        }

        float corr[4];
#pragma unroll
        for (int r = 0; r < 4; r++) {
            if (s0samp == qSamp[r]) sv0[r] = -1e30f;
            if (s1samp == qSamp[r]) sv1[r] = -1e30f;
            float m = fmaxf(sv0[r], sv1[r]);
#pragma unroll
            for (int off = 16; off > 0; off >>= 1)
                m = fmaxf(m, __shfl_xor_sync(0xffffffffu, m, off));
            float mnew = fmaxf(mrow[r], m);
            corr[r] = __expf(mrow[r] - mnew);
            mrow[r] = mnew;
            float p0 = __expf(sv0[r] - mnew);
            float p1 = __expf(sv1[r] - mnew);
            Ps[(4 * w + r) * 64 + lane]      = p0;
            Ps[(4 * w + r) * 64 + lane + 32] = p1;
            float ls = p0 + p1;
#pragma unroll
            for (int off = 16; off > 0; off >>= 1)
                ls += __shfl_xor_sync(0xffffffffu, ls, off);
            lrow[r] = lrow[r] * corr[r] + ls;
        }
        __syncwarp();

        float cLo = corr[rl], cHi = corr[rl + 2];
        oLo.x *= cLo; oLo.y *= cLo; oLo.z *= cLo; oLo.w *= cLo;
        oHi.x *= cHi; oHi.y *= cHi; oHi.z *= cHi; oHi.w *= cHi;

        const float* PsLo = Ps + (4 * w + rl) * 64;
        const float* PsHi = Ps + (4 * w + rl + 2) * 64;
#pragma unroll 8
        for (int c = 0; c < 64; c++) {
            float4 vv = Vs4[c * 16 + e4];
            float plo = PsLo[c], phi = PsHi[c];
            oLo.x = fmaf(plo, vv.x, oLo.x); oLo.y = fmaf(plo, vv.y, oLo.y);
            oLo.z = fmaf(plo, vv.z, oLo.z); oLo.w = fmaf(plo, vv.w, oLo.w);
            oHi.x = fmaf(phi, vv.x, oHi.x); oHi.y = fmaf(phi, vv.y, oHi.y);
            oHi.z = fmaf(phi, vv.z, oHi.z); oHi.w = fmaf(phi, vv.w, oHi.w);
        }
    }

    // write unnormalized partials
    int rowLo = qBase + 4 * w + rl;
    int rowHi = rowLo + 2;
    float* Op = g_Opart[sp];
    ((float4*)Op)[rowLo * 16 + e4] = oLo;
    ((float4*)Op)[rowHi * 16 + e4] = oHi;
    if (lane < 4) {
        int row = qBase + 4 * w + lane;
        g_mpart[sp][row] = mrow[lane];
        g_lpart[sp][row] = lrow[lane];
    }
}

// ============================================================
// Kernel E: combine split-K partials.
// ============================================================
__global__ __launch_bounds__(256) void cs_combine_kernel(float* __restrict__ outX)
{
    int g = blockIdx.x * 256 + threadIdx.x;   // over 6400*16 float4s
    int row = g >> 4;
    int e4 = g & 15;
    if (row >= N_ROWS) return;

    float m0 = g_mpart[0][row], m1 = g_mpart[1][row], m2 = g_mpart[2][row];
    float M = fmaxf(m0, fmaxf(m1, m2));
    float w0 = __expf(m0 - M), w1 = __expf(m1 - M), w2 = __expf(m2 - M);
    float denom = w0 * g_lpart[0][row] + w1 * g_lpart[1][row] + w2 * g_lpart[2][row];
    float inv = 1.f / denom;

    float4 a = ((const float4*)g_Opart[0])[row * 16 + e4];
    float4 b = ((const float4*)g_Opart[1])[row * 16 + e4];
    float4 c = ((const float4*)g_Opart[2])[row * 16 + e4];
    float4 o;
    o.x = (a.x * w0 + b.x * w1 + c.x * w2) * inv;
    o.y = (a.y * w0 + b.y * w1 + c.y * w2) * inv;
    o.z = (a.z * w0 + b.z * w1 + c.z * w2) * inv;
    o.w = (a.w * w0 + b.w * w1 + c.w * w2) * inv;
    ((float4*)outX)[row * 16 + e4] = o;
}

// ============================================================
extern "C" void kernel_launch(void* const* d_in, const int* in_sizes, int n_in,
                              void* d_out, int out_size)
{
    const float* x    = (const float*)d_in[0];
    const float* cb   = (const float*)d_in[1];
    const float* Wqis = (const float*)d_in[2];  const float* bqis = (const float*)d_in[3];
    const float* Wkis = (const float*)d_in[4];  const float* bkis = (const float*)d_in[5];
    const float* Wvis = (const float*)d_in[6];  const float* bvis = (const float*)d_in[7];
    const float* Wqcs = (const float*)d_in[8];  const float* bqcs = (const float*)d_in[9];
    const float* Wkcs = (const float*)d_in[10]; const float* bkcs = (const float*)d_in[11];
    const float* Wvcs = (const float*)d_in[12]; const float* bvcs = (const float*)d_in[13];
    float* out = (float*)d_out;

    proj_kernel<<<100, 256>>>(x, Wqis, bqis, Wkis, bkis, Wvis, bvis,
                                 Wqcs, bqcs, Wkcs, bkcs, Wvcs, bvcs);
    cs_attn_split_kernel<<<200 * NSPLIT, 256>>>();
    quant_kernel<<<200, 256>>>(x, cb, out);                    // quantized @ 0
    is_attn_kernel<<<128, 256>>>(out + N_ROWS * DIMV);         // Z @ 409600
    cs_combine_kernel<<<(N_ROWS * 16 + 255) / 256, 256>>>(out + 2 * N_ROWS * DIMV);
}

// round 4
// speedup vs baseline: 3.6197x; 2.6529x over previous
#include <cuda_runtime.h>
#include <cstdint>

#define N_ROWS 6400
#define DIMV 64
#define NUM_EMB 512
#define GROUP 100
#define NSPLIT 4
#define TILES_PER_SPLIT 25   // 4*25 = 100 key tiles of 64

// ---- scratch (no cudaMalloc allowed) ----
__device__ float g_qis[N_ROWS * DIMV];
__device__ float g_kis[N_ROWS * DIMV];
__device__ float g_vis[N_ROWS * DIMV];
__device__ float g_qcs[N_ROWS * DIMV];
__device__ float g_kcs[N_ROWS * DIMV];
__device__ float g_vcs[N_ROWS * DIMV];
__device__ float g_Opart[NSPLIT][N_ROWS * DIMV];
__device__ float g_mpart[NSPLIT][N_ROWS];
__device__ float g_lpart[NSPLIT][N_ROWS];

__device__ __forceinline__ uint32_t f2tf(float f) {
    uint32_t u;
    asm("cvt.rna.tf32.f32 %0, %1;" : "=r"(u) : "f"(f));
    return u;
}

__device__ __forceinline__ void mma_tf32(
    float& d0, float& d1, float& d2, float& d3,
    uint32_t a0, uint32_t a1, uint32_t a2, uint32_t a3,
    uint32_t b0, uint32_t b1)
{
    asm volatile(
        "mma.sync.aligned.m16n8k8.row.col.f32.tf32.tf32.f32 "
        "{%0,%1,%2,%3},{%4,%5,%6,%7},{%8,%9},{%0,%1,%2,%3};\n"
        : "+f"(d0), "+f"(d1), "+f"(d2), "+f"(d3)
        : "r"(a0), "r"(a1), "r"(a2), "r"(a3), "r"(b0), "r"(b1));
}

// ============================================================
// Kernel A: projections, one (proj, 64-row block) per CTA. grid 600.
// ============================================================
__global__ __launch_bounds__(256) void proj_kernel(
    const float* __restrict__ x,
    const float* __restrict__ W0, const float* __restrict__ b0,
    const float* __restrict__ W1, const float* __restrict__ b1,
    const float* __restrict__ W2, const float* __restrict__ b2,
    const float* __restrict__ W3, const float* __restrict__ b3,
    const float* __restrict__ W4, const float* __restrict__ b4,
    const float* __restrict__ W5, const float* __restrict__ b5)
{
    __shared__ float xs[64 * 64];
    __shared__ float Ws[64 * 64];
    __shared__ float bs[64];
    int p = blockIdx.x / 100;
    int rowBase = (blockIdx.x % 100) * 64;

    const float* Wl[6] = {W0, W1, W2, W3, W4, W5};
    const float* bl[6] = {b0, b1, b2, b3, b4, b5};
    float* ol[6] = {g_qis, g_kis, g_vis, g_qcs, g_kcs, g_vcs};
    const float* W = Wl[p];
    float* o = ol[p];

    for (int i = threadIdx.x; i < 64 * 64; i += 256) {
        xs[i] = x[rowBase * 64 + i];
        Ws[i] = W[i];
    }
    if (threadIdx.x < 64) bs[threadIdx.x] = bl[p][threadIdx.x];
    __syncthreads();

    int w = threadIdx.x >> 5, lane = threadIdx.x & 31;
    float a0[8], a1[8];
#pragma unroll
    for (int r = 0; r < 8; r++) { a0[r] = 0.f; a1[r] = 0.f; }
    for (int d = 0; d < 64; d++) {
        float w0 = Ws[d * 64 + lane];
        float w1 = Ws[d * 64 + lane + 32];
#pragma unroll
        for (int r = 0; r < 8; r++) {
            float xv = xs[(8 * w + r) * 64 + d];
            a0[r] = fmaf(xv, w0, a0[r]);
            a1[r] = fmaf(xv, w1, a1[r]);
        }
    }
    float bb0 = bs[lane], bb1 = bs[lane + 32];
#pragma unroll
    for (int r = 0; r < 8; r++) {
        int row = rowBase + 8 * w + r;
        o[row * 64 + lane]      = a0[r] + bb0;
        o[row * 64 + lane + 32] = a1[r] + bb1;
    }
}

// ============================================================
// Kernel B: vector quantization (argmin over 512 codes) + gather
// ============================================================
__global__ __launch_bounds__(256) void quant_kernel(
    const float* __restrict__ x, const float* __restrict__ cb,
    float* __restrict__ outQ)
{
    __shared__ float fs[32 * 68];
    __shared__ float cs[64 * 68];
    int rowBase = blockIdx.x * 32;
    for (int i = threadIdx.x; i < 32 * 64; i += 256)
        fs[(i >> 6) * 68 + (i & 63)] = x[rowBase * 64 + i];

    int w = threadIdx.x >> 5, lane = threadIdx.x & 31;
    float bestd[4]; int besti[4];
#pragma unroll
    for (int r = 0; r < 4; r++) { bestd[r] = 3.4e38f; besti[r] = 0; }

    const float4* fs4 = (const float4*)fs;
    const float4* cs4 = (const float4*)cs;

    for (int ch = 0; ch < 8; ch++) {
        __syncthreads();
        for (int i = threadIdx.x; i < 64 * 64; i += 256)
            cs[(i >> 6) * 68 + (i & 63)] = cb[ch * 64 * 64 + i];
        __syncthreads();

        float d0[4], d1[4];
#pragma unroll
        for (int r = 0; r < 4; r++) { d0[r] = 0.f; d1[r] = 0.f; }
#pragma unroll 4
        for (int q = 0; q < 16; q++) {
            float4 c0 = cs4[lane * 17 + q];
            float4 c1 = cs4[(lane + 32) * 17 + q];
#pragma unroll
            for (int r = 0; r < 4; r++) {
                float4 f = fs4[(4 * w + r) * 17 + q];
                float t;
                t = f.x - c0.x; d0[r] = fmaf(t, t, d0[r]);
                t = f.y - c0.y; d0[r] = fmaf(t, t, d0[r]);
                t = f.z - c0.z; d0[r] = fmaf(t, t, d0[r]);
                t = f.w - c0.w; d0[r] = fmaf(t, t, d0[r]);
                t = f.x - c1.x; d1[r] = fmaf(t, t, d1[r]);
                t = f.y - c1.y; d1[r] = fmaf(t, t, d1[r]);
                t = f.z - c1.z; d1[r] = fmaf(t, t, d1[r]);
                t = f.w - c1.w; d1[r] = fmaf(t, t, d1[r]);
            }
        }
#pragma unroll
        for (int r = 0; r < 4; r++) {
            int i0 = ch * 64 + lane;
            if (d0[r] < bestd[r]) { bestd[r] = d0[r]; besti[r] = i0; }
            if (d1[r] < bestd[r]) { bestd[r] = d1[r]; besti[r] = i0 + 32; }
        }
    }
#pragma unroll
    for (int r = 0; r < 4; r++) {
#pragma unroll
        for (int off = 16; off > 0; off >>= 1) {
            float ob = __shfl_xor_sync(0xffffffffu, bestd[r], off);
            int   oi = __shfl_xor_sync(0xffffffffu, besti[r], off);
            if (ob < bestd[r] || (ob == bestd[r] && oi < besti[r])) {
                bestd[r] = ob; besti[r] = oi;
            }
        }
        int idx = besti[r];
        int row = rowBase + 4 * w + r;
        outQ[row * 64 + lane]      = cb[idx * 64 + lane];
        outQ[row * 64 + lane + 32] = cb[idx * 64 + lane + 32];
    }
}

// ============================================================
// Kernel C: intra-sample attention. grid 256 (two CTAs per (b,d)).
// ============================================================
__global__ __launch_bounds__(256) void is_attn_kernel(float* __restrict__ outZ)
{
    __shared__ float qs[64 * 68];
    __shared__ float ks[50 * 64];
    __shared__ float vs[50 * 64];
    __shared__ float pbuf[8 * 64];

    int base = (blockIdx.x >> 1) * 50;
    int half = blockIdx.x & 1;
    for (int i = threadIdx.x; i < 50 * 64; i += 256) {
        int r = i >> 6, c = i & 63;
        qs[r * 68 + c] = g_qis[base * 64 + i];
        ks[i] = g_kis[base * 64 + i];
        vs[i] = g_vis[base * 64 + i];
    }
    __syncthreads();

    int w = threadIdx.x >> 5, lane = threadIdx.x & 31;
    const float4* qs4 = (const float4*)qs;
    const float4* ks4 = (const float4*)ks;

    for (int s = 8 * half + w; s < 50; s += 16) {
        int t1 = lane + 32;
        float a0 = 0.f, a1 = 0.f;
#pragma unroll 4
        for (int q = 0; q < 16; q++) {
            float4 kv = ks4[s * 16 + q];
            float4 q0 = qs4[lane * 17 + q];
            float4 q1 = qs4[t1 * 17 + q];
            a0 = fmaf(kv.x, q0.x, a0); a0 = fmaf(kv.y, q0.y, a0);
            a0 = fmaf(kv.z, q0.z, a0); a0 = fmaf(kv.w, q0.w, a0);
            a1 = fmaf(kv.x, q1.x, a1); a1 = fmaf(kv.y, q1.y, a1);
            a1 = fmaf(kv.z, q1.z, a1); a1 = fmaf(kv.w, q1.w, a1);
        }
        float s0 = a0;
        float s1 = (t1 < 50) ? a1 : -1e30f;
        float m = fmaxf(s0, s1);
#pragma unroll
        for (int off = 16; off > 0; off >>= 1)
            m = fmaxf(m, __shfl_xor_sync(0xffffffffu, m, off));
        float p0 = __expf(s0 - m);
        float p1 = (t1 < 50) ? __expf(s1 - m) : 0.f;
        float ls = p0 + p1;
#pragma unroll
        for (int off = 16; off > 0; off >>= 1)
            ls += __shfl_xor_sync(0xffffffffu, ls, off);

        pbuf[w * 64 + lane] = p0;
        pbuf[w * 64 + t1]   = p1;
        __syncwarp();

        float z0 = 0.f, z1 = 0.f;
#pragma unroll 5
        for (int t = 0; t < 50; t++) {
            float p = pbuf[w * 64 + t];
            z0 = fmaf(p, vs[t * 64 + lane], z0);
            z1 = fmaf(p, vs[t * 64 + lane + 32], z1);
        }
        float inv = 1.f / ls;
        outZ[(base + s) * 64 + lane]      = z0 * inv;
        outZ[(base + s) * 64 + lane + 32] = z1 * inv;
        __syncwarp();
    }
}

// ============================================================
// Kernel D: CS attention, flash + split-K, tf32 mma.sync.
// CTA: 128 threads (4 warps), M=64 q-rows, key tile 64.
// Dynamic smem 64KB: Qs | Ks | Vs | Ps (4096 words each).
// ============================================================
__global__ __launch_bounds__(128) void cs_attn_split_kernel()
{
    extern __shared__ uint32_t smbuf[];
    uint32_t* Qs = smbuf;
    uint32_t* Ks = smbuf + 4096;
    uint32_t* Vs = smbuf + 8192;
    uint32_t* Ps = smbuf + 12288;

    int qt = blockIdx.x >> 2, sp = blockIdx.x & 3;
    int qBase = qt * 64;
    int t = threadIdx.x;
    int wm = t >> 5, lane = t & 31;
    int g = lane >> 2, c4 = lane & 3;
    int r0 = wm * 16 + g;           // local row (second row r0+8)

    // ---- load Q tile (g_kcs rows qBase..qBase+64), tf32, swizzled ----
    {
        const float4* Qg = (const float4*)(g_kcs + qBase * 64);
        for (int i = t; i < 1024; i += 128) {
            int row = i >> 4, j = i & 15;
            float4 f = Qg[i];
            *(uint4*)(Qs + row * 64 + 4 * (j ^ (row & 7))) =
                make_uint4(f2tf(f.x), f2tf(f.y), f2tf(f.z), f2tf(f.w));
        }
    }

    float S[8][4];
    float O[8][4];
#pragma unroll
    for (int n = 0; n < 8; n++)
#pragma unroll
        for (int j = 0; j < 4; j++) O[n][j] = 0.f;

    float mA = -1e30f, mB = -1e30f, lA = 0.f, lB = 0.f;
    int qsA = (qBase + r0) / GROUP;
    int qsB = (qBase + r0 + 8) / GROUP;

    int ktStart = sp * TILES_PER_SPLIT;
    for (int kt = ktStart; kt < ktStart + TILES_PER_SPLIT; kt++) {
        __syncthreads();
        int kBase = kt * 64;
        // ---- load K,V tiles (row-major, d ^ 8*(key&3) swizzle), tf32 ----
        {
            const float4* Kg = (const float4*)(g_qcs + kBase * 64);
            const float4* Vg = (const float4*)(g_vcs + kBase * 64);
            for (int i = t; i < 1024; i += 128) {
                int key = i >> 4, j = i & 15;
                int w0 = key * 64 + 4 * (j ^ (2 * (key & 3)));
                float4 a = Kg[i];
                *(uint4*)(Ks + w0) = make_uint4(f2tf(a.x), f2tf(a.y), f2tf(a.z), f2tf(a.w));
                float4 b = Vg[i];
                *(uint4*)(Vs + w0) = make_uint4(f2tf(b.x), f2tf(b.y), f2tf(b.z), f2tf(b.w));
            }
        }
        __syncthreads();

        // ---- S = Q . K^T  (m16 x n64, k=64) ----
#pragma unroll
        for (int n = 0; n < 8; n++)
#pragma unroll
            for (int j = 0; j < 4; j++) S[n][j] = 0.f;

#pragma unroll
        for (int k0 = 0; k0 < 8; k0++) {
            int ca = k0 * 8 + c4;
            uint32_t a0 = Qs[r0 * 64 + (ca ^ (4 * g))];
            uint32_t a1 = Qs[(r0 + 8) * 64 + (ca ^ (4 * g))];
            uint32_t a2 = Qs[r0 * 64 + ((ca + 4) ^ (4 * g))];
            uint32_t a3 = Qs[(r0 + 8) * 64 + ((ca + 4) ^ (4 * g))];
#pragma unroll
            for (int n0 = 0; n0 < 8; n0++) {
                int key = n0 * 8 + g;
                uint32_t b0 = Ks[key * 64 + (ca ^ (8 * (key & 3)))];
                uint32_t b1 = Ks[key * 64 + ((ca + 4) ^ (8 * (key & 3)))];
                mma_tf32(S[n0][0], S[n0][1], S[n0][2], S[n0][3],
                         a0, a1, a2, a3, b0, b1);
            }
        }

        // ---- mask + online softmax ----
        float rmA = -1e30f, rmB = -1e30f;
#pragma unroll
        for (int n0 = 0; n0 < 8; n0++) {
            int col0 = kBase + n0 * 8 + 2 * c4;
            int s0 = col0 / GROUP, s1 = (col0 + 1) / GROUP;
            if (s0 == qsA) S[n0][0] = -1e30f;
            if (s1 == qsA) S[n0][1] = -1e30f;
            if (s0 == qsB) S[n0][2] = -1e30f;
            if (s1 == qsB) S[n0][3] = -1e30f;
            rmA = fmaxf(rmA, fmaxf(S[n0][0], S[n0][1]));
            rmB = fmaxf(rmB, fmaxf(S[n0][2], S[n0][3]));
        }
        rmA = fmaxf(rmA, __shfl_xor_sync(0xffffffffu, rmA, 1));
        rmA = fmaxf(rmA, __shfl_xor_sync(0xffffffffu, rmA, 2));
        rmB = fmaxf(rmB, __shfl_xor_sync(0xffffffffu, rmB, 1));
        rmB = fmaxf(rmB, __shfl_xor_sync(0xffffffffu, rmB, 2));

        float mAn = fmaxf(mA, rmA), mBn = fmaxf(mB, rmB);
        float corrA = __expf(mA - mAn), corrB = __expf(mB - mBn);
        mA = mAn; mB = mBn;

        float lsA = 0.f, lsB = 0.f;
#pragma unroll
        for (int n0 = 0; n0 < 8; n0++) {
            float pA0 = __expf(S[n0][0] - mA);
            float pA1 = __expf(S[n0][1] - mA);
            float pB0 = __expf(S[n0][2] - mB);
            float pB1 = __expf(S[n0][3] - mB);
            lsA += pA0 + pA1;
            lsB += pB0 + pB1;
            int cl = n0 * 8 + 2 * c4;
            *(uint2*)(Ps + r0 * 64 + (cl ^ (4 * g))) = make_uint2(f2tf(pA0), f2tf(pA1));
            *(uint2*)(Ps + (r0 + 8) * 64 + (cl ^ (4 * g))) = make_uint2(f2tf(pB0), f2tf(pB1));
            O[n0][0] *= corrA; O[n0][1] *= corrA;
            O[n0][2] *= corrB; O[n0][3] *= corrB;
        }
        lsA += __shfl_xor_sync(0xffffffffu, lsA, 1);
        lsA += __shfl_xor_sync(0xffffffffu, lsA, 2);
        lsB += __shfl_xor_sync(0xffffffffu, lsB, 1);
        lsB += __shfl_xor_sync(0xffffffffu, lsB, 2);
        lA = lA * corrA + lsA;
        lB = lB * corrB + lsB;
        __syncwarp();

        // ---- O += P . V  (k = 64 keys, n = 64 dims) ----
#pragma unroll
        for (int k0 = 0; k0 < 8; k0++) {
            int ca = k0 * 8 + c4;
            uint32_t a0 = Ps[r0 * 64 + (ca ^ (4 * g))];
            uint32_t a1 = Ps[(r0 + 8) * 64 + (ca ^ (4 * g))];
            uint32_t a2 = Ps[r0 * 64 + ((ca + 4) ^ (4 * g))];
            uint32_t a3 = Ps[(r0 + 8) * 64 + ((ca + 4) ^ (4 * g))];
            int ky0 = k0 * 8 + c4;       // key row for b0 (&3 == c4)
            int ky1 = ky0 + 4;           // key row for b1 (&3 == c4)
#pragma unroll
            for (int n0 = 0; n0 < 8; n0++) {
                int dcol = n0 * 8 + g;
                uint32_t b0 = Vs[ky0 * 64 + (dcol ^ (8 * c4))];
                uint32_t b1 = Vs[ky1 * 64 + (dcol ^ (8 * c4))];
                mma_tf32(O[n0][0], O[n0][1], O[n0][2], O[n0][3],
                         a0, a1, a2, a3, b0, b1);
            }
        }
    }

    // ---- write unnormalized partials ----
    float* Op = g_Opart[sp];
    int rowA = qBase + r0, rowB = rowA + 8;
#pragma unroll
    for (int n0 = 0; n0 < 8; n0++) {
        int col = n0 * 8 + 2 * c4;
        *(float2*)(Op + rowA * 64 + col) = make_float2(O[n0][0], O[n0][1]);
        *(float2*)(Op + rowB * 64 + col) = make_float2(O[n0][2], O[n0][3]);
    }
    if (c4 == 0) {
        g_mpart[sp][rowA] = mA; g_lpart[sp][rowA] = lA;
        g_mpart[sp][rowB] = mB; g_lpart[sp][rowB] = lB;
    }
}

// ============================================================
// Kernel E: combine split-K partials.
// ============================================================
__global__ __launch_bounds__(256) void cs_combine_kernel(float* __restrict__ outX)
{
    int gidx = blockIdx.x * 256 + threadIdx.x;   // over 6400*16 float4s
    int row = gidx >> 4;
    int e4 = gidx & 15;
    if (row >= N_ROWS) return;

    float m[NSPLIT];
    float M = -3.4e38f;
#pragma unroll
    for (int s = 0; s < NSPLIT; s++) { m[s] = g_mpart[s][row]; M = fmaxf(M, m[s]); }
    float wgt[NSPLIT];
    float denom = 0.f;
#pragma unroll
    for (int s = 0; s < NSPLIT; s++) {
        wgt[s] = __expf(m[s] - M);
        denom += wgt[s] * g_lpart[s][row];
    }
    float inv = 1.f / denom;

    float4 o = {0.f, 0.f, 0.f, 0.f};
#pragma unroll
    for (int s = 0; s < NSPLIT; s++) {
        float4 a = ((const float4*)g_Opart[s])[row * 16 + e4];
        o.x = fmaf(a.x, wgt[s], o.x);
        o.y = fmaf(a.y, wgt[s], o.y);
        o.z = fmaf(a.z, wgt[s], o.z);
        o.w = fmaf(a.w, wgt[s], o.w);
    }
    o.x *= inv; o.y *= inv; o.z *= inv; o.w *= inv;
    ((float4*)outX)[row * 16 + e4] = o;
}

// ============================================================
extern "C" void kernel_launch(void* const* d_in, const int* in_sizes, int n_in,
                              void* d_out, int out_size)
{
    const float* x    = (const float*)d_in[0];
    const float* cb   = (const float*)d_in[1];
    const float* Wqis = (const float*)d_in[2];  const float* bqis = (const float*)d_in[3];
    const float* Wkis = (const float*)d_in[4];  const float* bkis = (const float*)d_in[5];
    const float* Wvis = (const float*)d_in[6];  const float* bvis = (const float*)d_in[7];
    const float* Wqcs = (const float*)d_in[8];  const float* bqcs = (const float*)d_in[9];
    const float* Wkcs = (const float*)d_in[10]; const float* bkcs = (const float*)d_in[11];
    const float* Wvcs = (const float*)d_in[12]; const float* bvcs = (const float*)d_in[13];
    float* out = (float*)d_out;

    cudaFuncSetAttribute(cs_attn_split_kernel,
                         cudaFuncAttributeMaxDynamicSharedMemorySize, 65536);

    proj_kernel<<<600, 256>>>(x, Wqis, bqis, Wkis, bkis, Wvis, bvis,
                              Wqcs, bqcs, Wkcs, bkcs, Wvcs, bvcs);
    cs_attn_split_kernel<<<100 * NSPLIT, 128, 65536>>>();
    quant_kernel<<<200, 256>>>(x, cb, out);                    // quantized @ 0
    is_attn_kernel<<<256, 256>>>(out + N_ROWS * DIMV);         // Z @ 409600
    cs_combine_kernel<<<(N_ROWS * 16 + 255) / 256, 256>>>(out + 2 * N_ROWS * DIMV);
}

// round 5
// speedup vs baseline: 4.7808x; 1.3208x over previous
#include <cuda_runtime.h>
#include <cstdint>

#define N_ROWS 6400
#define DIMV 64
#define NUM_EMB 512
#define GROUP 100
#define NSPLIT 6
#define TILES_PER_SPLIT 17   // 5*17 + 15 = 100 key tiles of 64

// ---- scratch (no cudaMalloc allowed) ----
__device__ float g_qis[N_ROWS * DIMV];
__device__ float g_kis[N_ROWS * DIMV];
__device__ float g_vis[N_ROWS * DIMV];
__device__ float g_qcs[N_ROWS * DIMV];
__device__ float g_kcs[N_ROWS * DIMV];
__device__ float g_vcs[N_ROWS * DIMV];
__device__ float g_Opart[NSPLIT][N_ROWS * DIMV];
__device__ float g_mpart[NSPLIT][N_ROWS];
__device__ float g_lpart[NSPLIT][N_ROWS];

__device__ __forceinline__ uint32_t f2tf(float f) {
    uint32_t u;
    asm("cvt.rna.tf32.f32 %0, %1;" : "=r"(u) : "f"(f));
    return u;
}

__device__ __forceinline__ void mma_tf32(
    float* d,
    uint32_t a0, uint32_t a1, uint32_t a2, uint32_t a3,
    uint32_t b0, uint32_t b1)
{
    asm volatile(
        "mma.sync.aligned.m16n8k8.row.col.f32.tf32.tf32.f32 "
        "{%0,%1,%2,%3},{%4,%5,%6,%7},{%8,%9},{%0,%1,%2,%3};\n"
        : "+f"(d[0]), "+f"(d[1]), "+f"(d[2]), "+f"(d[3])
        : "r"(a0), "r"(a1), "r"(a2), "r"(a3), "r"(b0), "r"(b1));
}

// ============================================================
// Kernel A: projections, one (proj, 64-row block) per CTA. grid 600.
// ============================================================
__global__ __launch_bounds__(256) void proj_kernel(
    const float* __restrict__ x,
    const float* __restrict__ W0, const float* __restrict__ b0,
    const float* __restrict__ W1, const float* __restrict__ b1,
    const float* __restrict__ W2, const float* __restrict__ b2,
    const float* __restrict__ W3, const float* __restrict__ b3,
    const float* __restrict__ W4, const float* __restrict__ b4,
    const float* __restrict__ W5, const float* __restrict__ b5)
{
    __shared__ float xs[64 * 64];
    __shared__ float Ws[64 * 64];
    __shared__ float bs[64];
    int p = blockIdx.x / 100;
    int rowBase = (blockIdx.x % 100) * 64;

    const float* Wl[6] = {W0, W1, W2, W3, W4, W5};
    const float* bl[6] = {b0, b1, b2, b3, b4, b5};
    float* ol[6] = {g_qis, g_kis, g_vis, g_qcs, g_kcs, g_vcs};
    const float* W = Wl[p];
    float* o = ol[p];

    for (int i = threadIdx.x; i < 64 * 64; i += 256) {
        xs[i] = x[rowBase * 64 + i];
        Ws[i] = W[i];
    }
    if (threadIdx.x < 64) bs[threadIdx.x] = bl[p][threadIdx.x];
    __syncthreads();

    int w = threadIdx.x >> 5, lane = threadIdx.x & 31;
    float a0[8], a1[8];
#pragma unroll
    for (int r = 0; r < 8; r++) { a0[r] = 0.f; a1[r] = 0.f; }
    for (int d = 0; d < 64; d++) {
        float w0 = Ws[d * 64 + lane];
        float w1 = Ws[d * 64 + lane + 32];
#pragma unroll
        for (int r = 0; r < 8; r++) {
            float xv = xs[(8 * w + r) * 64 + d];
            a0[r] = fmaf(xv, w0, a0[r]);
            a1[r] = fmaf(xv, w1, a1[r]);
        }
    }
    float bb0 = bs[lane], bb1 = bs[lane + 32];
#pragma unroll
    for (int r = 0; r < 8; r++) {
        int row = rowBase + 8 * w + r;
        o[row * 64 + lane]      = a0[r] + bb0;
        o[row * 64 + lane + 32] = a1[r] + bb1;
    }
}

// ============================================================
// Kernel B: vector quantization. dist = ||c||^2 - 2 f.c (argmin
// invariant to the dropped ||f||^2). 4 chunks of 128 codes, 4x4
// register blocking. grid 200 x 256, 32 rows per CTA.
// ============================================================
__global__ __launch_bounds__(256) void quant_kernel(
    const float* __restrict__ x, const float* __restrict__ cb,
    float* __restrict__ outQ)
{
    __shared__ float fs[32 * 68];
    __shared__ float cs[128 * 68];
    __shared__ float cn[128];
    int rowBase = blockIdx.x * 32;
    for (int i = threadIdx.x; i < 32 * 64; i += 256)
        fs[(i >> 6) * 68 + (i & 63)] = x[rowBase * 64 + i];

    int w = threadIdx.x >> 5, lane = threadIdx.x & 31;
    float bestd[4]; int besti[4];
#pragma unroll
    for (int r = 0; r < 4; r++) { bestd[r] = 3.4e38f; besti[r] = 0; }

    const float4* fs4 = (const float4*)fs;
    const float4* cs4 = (const float4*)cs;

    for (int ch = 0; ch < 4; ch++) {
        __syncthreads();
        for (int i = threadIdx.x; i < 128 * 64; i += 256)
            cs[(i >> 6) * 68 + (i & 63)] = cb[ch * 128 * 64 + i];
        __syncthreads();
        if (threadIdx.x < 128) {
            float s = 0.f;
#pragma unroll 4
            for (int q = 0; q < 16; q++) {
                float4 c = cs4[threadIdx.x * 17 + q];
                s = fmaf(c.x, c.x, s); s = fmaf(c.y, c.y, s);
                s = fmaf(c.z, c.z, s); s = fmaf(c.w, c.w, s);
            }
            cn[threadIdx.x] = s;
        }
        __syncthreads();

        float d[4][4];
#pragma unroll
        for (int r = 0; r < 4; r++)
#pragma unroll
            for (int j = 0; j < 4; j++) d[r][j] = 0.f;

#pragma unroll 4
        for (int q = 0; q < 16; q++) {
            float4 cv[4];
#pragma unroll
            for (int j = 0; j < 4; j++) cv[j] = cs4[(j * 32 + lane) * 17 + q];
#pragma unroll
            for (int r = 0; r < 4; r++) {
                float4 f = fs4[(4 * w + r) * 17 + q];
#pragma unroll
                for (int j = 0; j < 4; j++) {
                    d[r][j] = fmaf(f.x, cv[j].x, d[r][j]);
                    d[r][j] = fmaf(f.y, cv[j].y, d[r][j]);
                    d[r][j] = fmaf(f.z, cv[j].z, d[r][j]);
                    d[r][j] = fmaf(f.w, cv[j].w, d[r][j]);
                }
            }
        }
#pragma unroll
        for (int r = 0; r < 4; r++) {
#pragma unroll
            for (int j = 0; j < 4; j++) {
                int ci = j * 32 + lane;
                float dist = cn[ci] - 2.f * d[r][j];
                int idx = ch * 128 + ci;
                if (dist < bestd[r] || (dist == bestd[r] && idx < besti[r])) {
                    bestd[r] = dist; besti[r] = idx;
                }
            }
        }
    }
#pragma unroll
    for (int r = 0; r < 4; r++) {
#pragma unroll
        for (int off = 16; off > 0; off >>= 1) {
            float ob = __shfl_xor_sync(0xffffffffu, bestd[r], off);
            int   oi = __shfl_xor_sync(0xffffffffu, besti[r], off);
            if (ob < bestd[r] || (ob == bestd[r] && oi < besti[r])) {
                bestd[r] = ob; besti[r] = oi;
            }
        }
        int idx = besti[r];
        int row = rowBase + 4 * w + r;
        outQ[row * 64 + lane]      = cb[idx * 64 + lane];
        outQ[row * 64 + lane + 32] = cb[idx * 64 + lane + 32];
    }
}

// ============================================================
// Kernel C: intra-sample attention. grid 512 (4 CTAs per (b,d)).
// ============================================================
__global__ __launch_bounds__(256) void is_attn_kernel(float* __restrict__ outZ)
{
    __shared__ float qs[64 * 68];
    __shared__ float ks[50 * 64];
    __shared__ float vs[50 * 64];
    __shared__ float pbuf[8 * 64];

    int base = (blockIdx.x >> 2) * 50;
    int quarter = blockIdx.x & 3;
    for (int i = threadIdx.x; i < 50 * 64; i += 256) {
        int r = i >> 6, c = i & 63;
        qs[r * 68 + c] = g_qis[base * 64 + i];
        ks[i] = g_kis[base * 64 + i];
        vs[i] = g_vis[base * 64 + i];
    }
    __syncthreads();

    int w = threadIdx.x >> 5, lane = threadIdx.x & 31;
    const float4* qs4 = (const float4*)qs;
    const float4* ks4 = (const float4*)ks;

    for (int s = 8 * quarter + w; s < 50; s += 32) {
        int t1 = lane + 32;
        float a0 = 0.f, a1 = 0.f;
#pragma unroll 4
        for (int q = 0; q < 16; q++) {
            float4 kv = ks4[s * 16 + q];
            float4 q0 = qs4[lane * 17 + q];
            float4 q1 = qs4[t1 * 17 + q];
            a0 = fmaf(kv.x, q0.x, a0); a0 = fmaf(kv.y, q0.y, a0);
            a0 = fmaf(kv.z, q0.z, a0); a0 = fmaf(kv.w, q0.w, a0);
            a1 = fmaf(kv.x, q1.x, a1); a1 = fmaf(kv.y, q1.y, a1);
            a1 = fmaf(kv.z, q1.z, a1); a1 = fmaf(kv.w, q1.w, a1);
        }
        float s0 = a0;
        float s1 = (t1 < 50) ? a1 : -1e30f;
        float m = fmaxf(s0, s1);
#pragma unroll
        for (int off = 16; off > 0; off >>= 1)
            m = fmaxf(m, __shfl_xor_sync(0xffffffffu, m, off));
        float p0 = __expf(s0 - m);
        float p1 = (t1 < 50) ? __expf(s1 - m) : 0.f;
        float ls = p0 + p1;
#pragma unroll
        for (int off = 16; off > 0; off >>= 1)
            ls += __shfl_xor_sync(0xffffffffu, ls, off);

        pbuf[w * 64 + lane] = p0;
        pbuf[w * 64 + t1]   = p1;
        __syncwarp();

        float z0 = 0.f, z1 = 0.f;
#pragma unroll 5
        for (int t = 0; t < 50; t++) {
            float p = pbuf[w * 64 + t];
            z0 = fmaf(p, vs[t * 64 + lane], z0);
            z1 = fmaf(p, vs[t * 64 + lane + 32], z1);
        }
        float inv = 1.f / ls;
        outZ[(base + s) * 64 + lane]      = z0 * inv;
        outZ[(base + s) * 64 + lane + 32] = z1 * inv;
        __syncwarp();
    }
}

// ============================================================
// Kernel D: CS attention, flash + split-K, tf32 mma.sync.
// CTA: 128 threads (4 warps), M=128 q-rows (32 rows/warp as two
// m16 blocks), key tile 64. 96KB dynamic smem: Q(8192w) K(4096w)
// V(4096w) P(8192w). K swizzle key&7 (conflict-free B loads),
// V swizzle 2*(key&3) (conflict-free PV B loads, as in R4).
// ============================================================
__global__ __launch_bounds__(128) void cs_attn_split_kernel()
{
    extern __shared__ uint32_t smbuf[];
    uint32_t* Qs = smbuf;            // 8192 words
    uint32_t* Ks = smbuf + 8192;     // 4096
    uint32_t* Vs = smbuf + 12288;    // 4096
    uint32_t* Ps = smbuf + 16384;    // 8192

    int qt = blockIdx.x / NSPLIT, sp = blockIdx.x % NSPLIT;
    int qBase = qt * 128;
    int t = threadIdx.x;
    int wm = t >> 5, lane = t & 31;
    int g = lane >> 2, c4 = lane & 3;

    // ---- load Q tile (128 rows of g_kcs), tf32, row&7 swizzle ----
    {
        const float4* Qg = (const float4*)(g_kcs + qBase * 64);
        for (int i = t; i < 2048; i += 128) {
            int row = i >> 4, j = i & 15;
            float4 f = Qg[i];
            *(uint4*)(Qs + row * 64 + 4 * (j ^ (row & 7))) =
                make_uint4(f2tf(f.x), f2tf(f.y), f2tf(f.z), f2tf(f.w));
        }
    }

    float S[2][8][4];
    float O[2][8][4];
#pragma unroll
    for (int b = 0; b < 2; b++)
#pragma unroll
        for (int n = 0; n < 8; n++)
#pragma unroll
            for (int j = 0; j < 4; j++) O[b][n][j] = 0.f;

    float mv[4], lv[4];
    int qsamp[4];
#pragma unroll
    for (int s = 0; s < 4; s++) {
        mv[s] = -1e30f; lv[s] = 0.f;
        int row = qBase + wm * 32 + (s >> 1) * 16 + (s & 1) * 8 + g;
        qsamp[s] = row / GROUP;
    }

    int ktStart = sp * TILES_PER_SPLIT;
    int ktEnd = ktStart + TILES_PER_SPLIT;
    if (ktEnd > 100) ktEnd = 100;

    for (int kt = ktStart; kt < ktEnd; kt++) {
        __syncthreads();
        int kBase = kt * 64;
        {
            const float4* Kg = (const float4*)(g_qcs + kBase * 64);
            const float4* Vg = (const float4*)(g_vcs + kBase * 64);
            for (int i = t; i < 1024; i += 128) {
                int key = i >> 4, j = i & 15;
                float4 a = Kg[i];
                *(uint4*)(Ks + key * 64 + 4 * (j ^ (key & 7))) =
                    make_uint4(f2tf(a.x), f2tf(a.y), f2tf(a.z), f2tf(a.w));
                float4 b = Vg[i];
                *(uint4*)(Vs + key * 64 + 4 * (j ^ (2 * (key & 3)))) =
                    make_uint4(f2tf(b.x), f2tf(b.y), f2tf(b.z), f2tf(b.w));
            }
        }
        __syncthreads();

        // ---- S = Q . K^T  (two m16 blocks x n64, k=64) ----
#pragma unroll
        for (int b = 0; b < 2; b++)
#pragma unroll
            for (int n = 0; n < 8; n++)
#pragma unroll
                for (int j = 0; j < 4; j++) S[b][n][j] = 0.f;

#pragma unroll
        for (int k0 = 0; k0 < 8; k0++) {
            int ch0 = 4 * ((2 * k0) ^ g);
            int ch1 = 4 * ((2 * k0 + 1) ^ g);
            uint32_t a[2][4];
#pragma unroll
            for (int b = 0; b < 2; b++) {
                int rL = (wm * 32 + b * 16 + g) * 64;
                a[b][0] = Qs[rL + ch0 + c4];
                a[b][1] = Qs[rL + 512 + ch0 + c4];   // row+8
                a[b][2] = Qs[rL + ch1 + c4];
                a[b][3] = Qs[rL + 512 + ch1 + c4];
            }
#pragma unroll
            for (int n0 = 0; n0 < 8; n0++) {
                int key = n0 * 8 + g;                // key&7 == g
                uint32_t b0 = Ks[key * 64 + ch0 + c4];
                uint32_t b1 = Ks[key * 64 + ch1 + c4];
                mma_tf32(S[0][n0], a[0][0], a[0][1], a[0][2], a[0][3], b0, b1);
                mma_tf32(S[1][n0], a[1][0], a[1][1], a[1][2], a[1][3], b0, b1);
            }
        }

        // ---- mask + online softmax (4 row streams) ----
        float rm[4] = {-1e30f, -1e30f, -1e30f, -1e30f};
#pragma unroll
        for (int n0 = 0; n0 < 8; n0++) {
            int col0 = kBase + n0 * 8 + 2 * c4;
            int cs0 = col0 / GROUP, cs1 = (col0 + 1) / GROUP;
#pragma unroll
            for (int s = 0; s < 4; s++) {
                int b = s >> 1, h = s & 1;
                if (cs0 == qsamp[s]) S[b][n0][2 * h]     = -1e30f;
                if (cs1 == qsamp[s]) S[b][n0][2 * h + 1] = -1e30f;
                rm[s] = fmaxf(rm[s], fmaxf(S[b][n0][2 * h], S[b][n0][2 * h + 1]));
            }
        }
        float corr[4];
#pragma unroll
        for (int s = 0; s < 4; s++) {
            rm[s] = fmaxf(rm[s], __shfl_xor_sync(0xffffffffu, rm[s], 1));
            rm[s] = fmaxf(rm[s], __shfl_xor_sync(0xffffffffu, rm[s], 2));
            float mn = fmaxf(mv[s], rm[s]);
            corr[s] = __expf(mv[s] - mn);
            mv[s] = mn;
        }
        float ls[4] = {0.f, 0.f, 0.f, 0.f};
#pragma unroll
        for (int n0 = 0; n0 < 8; n0++) {
            int chp = 4 * ((2 * n0 + (c4 >> 1)) ^ g) + ((2 * c4) & 3);
#pragma unroll
            for (int s = 0; s < 4; s++) {
                int b = s >> 1, h = s & 1;
                float p0 = __expf(S[b][n0][2 * h]     - mv[s]);
                float p1 = __expf(S[b][n0][2 * h + 1] - mv[s]);
                ls[s] += p0 + p1;
                int row = wm * 32 + b * 16 + h * 8 + g;
                *(uint2*)(Ps + row * 64 + chp) = make_uint2(f2tf(p0), f2tf(p1));
            }
        }
#pragma unroll
        for (int s = 0; s < 4; s++) {
            ls[s] += __shfl_xor_sync(0xffffffffu, ls[s], 1);
            ls[s] += __shfl_xor_sync(0xffffffffu, ls[s], 2);
            lv[s] = lv[s] * corr[s] + ls[s];
            int b = s >> 1, h = s & 1;
#pragma unroll
            for (int n0 = 0; n0 < 8; n0++) {
                O[b][n0][2 * h]     *= corr[s];
                O[b][n0][2 * h + 1] *= corr[s];
            }
        }
        __syncwarp();

        // ---- O += P . V ----
#pragma unroll
        for (int k0 = 0; k0 < 8; k0++) {
            int ch0 = 4 * ((2 * k0) ^ g);
            int ch1 = 4 * ((2 * k0 + 1) ^ g);
            uint32_t a[2][4];
#pragma unroll
            for (int b = 0; b < 2; b++) {
                int rL = (wm * 32 + b * 16 + g) * 64;
                a[b][0] = Ps[rL + ch0 + c4];
                a[b][1] = Ps[rL + 512 + ch0 + c4];
                a[b][2] = Ps[rL + ch1 + c4];
                a[b][3] = Ps[rL + 512 + ch1 + c4];
            }
            int ky0 = (k0 * 8 + c4) * 64;
            int ky1 = ky0 + 256;                 // +4 keys, same (key&3)
            int sw = 2 * c4;
#pragma unroll
            for (int n0 = 0; n0 < 8; n0++) {
                int ch = 4 * ((2 * n0 + (g >> 2)) ^ sw) + (g & 3);
                uint32_t b0 = Vs[ky0 + ch];
                uint32_t b1 = Vs[ky1 + ch];
                mma_tf32(O[0][n0], a[0][0], a[0][1], a[0][2], a[0][3], b0, b1);
                mma_tf32(O[1][n0], a[1][0], a[1][1], a[1][2], a[1][3], b0, b1);
            }
        }
    }

    // ---- write unnormalized partials ----
    float* Op = g_Opart[sp];
#pragma unroll
    for (int b = 0; b < 2; b++) {
        int rowA = qBase + wm * 32 + b * 16 + g;
#pragma unroll
        for (int n0 = 0; n0 < 8; n0++) {
            int col = n0 * 8 + 2 * c4;
            *(float2*)(Op + rowA * 64 + col)       = make_float2(O[b][n0][0], O[b][n0][1]);
            *(float2*)(Op + (rowA + 8) * 64 + col) = make_float2(O[b][n0][2], O[b][n0][3]);
        }
    }
    if (c4 == 0) {
#pragma unroll
        for (int s = 0; s < 4; s++) {
            int row = qBase + wm * 32 + (s >> 1) * 16 + (s & 1) * 8 + g;
            g_mpart[sp][row] = mv[s];
            g_lpart[sp][row] = lv[s];
        }
    }
}

// ============================================================
// Kernel E: combine split-K partials.
// ============================================================
__global__ __launch_bounds__(256) void cs_combine_kernel(float* __restrict__ outX)
{
    int gidx = blockIdx.x * 256 + threadIdx.x;   // over 6400*16 float4s
    int row = gidx >> 4;
    int e4 = gidx & 15;
    if (row >= N_ROWS) return;

    float m[NSPLIT];
    float M = -3.4e38f;
#pragma unroll
    for (int s = 0; s < NSPLIT; s++) { m[s] = g_mpart[s][row]; M = fmaxf(M, m[s]); }
    float wgt[NSPLIT];
    float denom = 0.f;
#pragma unroll
    for (int s = 0; s < NSPLIT; s++) {
        wgt[s] = __expf(m[s] - M);
        denom += wgt[s] * g_lpart[s][row];
    }
    float inv = 1.f / denom;

    float4 o = {0.f, 0.f, 0.f, 0.f};
#pragma unroll
    for (int s = 0; s < NSPLIT; s++) {
        float4 a = ((const float4*)g_Opart[s])[row * 16 + e4];
        o.x = fmaf(a.x, wgt[s], o.x);
        o.y = fmaf(a.y, wgt[s], o.y);
        o.z = fmaf(a.z, wgt[s], o.z);
        o.w = fmaf(a.w, wgt[s], o.w);
    }
    o.x *= inv; o.y *= inv; o.z *= inv; o.w *= inv;
    ((float4*)outX)[row * 16 + e4] = o;
}

// ============================================================
extern "C" void kernel_launch(void* const* d_in, const int* in_sizes, int n_in,
                              void* d_out, int out_size)
{
    const float* x    = (const float*)d_in[0];
    const float* cb   = (const float*)d_in[1];
    const float* Wqis = (const float*)d_in[2];  const float* bqis = (const float*)d_in[3];
    const float* Wkis = (const float*)d_in[4];  const float* bkis = (const float*)d_in[5];
    const float* Wvis = (const float*)d_in[6];  const float* bvis = (const float*)d_in[7];
    const float* Wqcs = (const float*)d_in[8];  const float* bqcs = (const float*)d_in[9];
    const float* Wkcs = (const float*)d_in[10]; const float* bkcs = (const float*)d_in[11];
    const float* Wvcs = (const float*)d_in[12]; const float* bvcs = (const float*)d_in[13];
    float* out = (float*)d_out;

    cudaFuncSetAttribute(cs_attn_split_kernel,
                         cudaFuncAttributeMaxDynamicSharedMemorySize, 98304);

    proj_kernel<<<600, 256>>>(x, Wqis, bqis, Wkis, bkis, Wvis, bvis,
                              Wqcs, bqcs, Wkcs, bkcs, Wvcs, bvcs);
    cs_attn_split_kernel<<<50 * NSPLIT, 128, 98304>>>();
    quant_kernel<<<200, 256>>>(x, cb, out);                    // quantized @ 0
    is_attn_kernel<<<512, 256>>>(out + N_ROWS * DIMV);         // Z @ 409600
    cs_combine_kernel<<<(N_ROWS * 16 + 255) / 256, 256>>>(out + 2 * N_ROWS * DIMV);
}

// round 6
// speedup vs baseline: 5.4997x; 1.1504x over previous
#include <cuda_runtime.h>
#include <cstdint>

#define N_ROWS 6400
#define DIMV 64
#define NUM_EMB 512
#define GROUP 100
#define NSPLIT 6
#define TILES_PER_SPLIT 17   // 5*17 + 15 = 100 key tiles of 64

// ---- scratch (no cudaMalloc allowed); +1024 pad so 64-row tile reads
// starting at row 6350 never read past the end ----
__device__ float g_qis[N_ROWS * DIMV + 1024];
__device__ float g_kis[N_ROWS * DIMV + 1024];
__device__ float g_vis[N_ROWS * DIMV + 1024];
__device__ float g_qcs[N_ROWS * DIMV + 1024];
__device__ float g_kcs[N_ROWS * DIMV + 1024];
__device__ float g_vcs[N_ROWS * DIMV + 1024];
__device__ float g_Opart[NSPLIT][N_ROWS * DIMV];
__device__ float g_mpart[NSPLIT][N_ROWS];
__device__ float g_lpart[NSPLIT][N_ROWS];

__device__ __forceinline__ uint32_t f2tf(float f) {
    uint32_t u;
    asm("cvt.rna.tf32.f32 %0, %1;" : "=r"(u) : "f"(f));
    return u;
}

__device__ __forceinline__ void mma_tf32(
    float* d,
    uint32_t a0, uint32_t a1, uint32_t a2, uint32_t a3,
    uint32_t b0, uint32_t b1)
{
    asm volatile(
        "mma.sync.aligned.m16n8k8.row.col.f32.tf32.tf32.f32 "
        "{%0,%1,%2,%3},{%4,%5,%6,%7},{%8,%9},{%0,%1,%2,%3};\n"
        : "+f"(d[0]), "+f"(d[1]), "+f"(d[2]), "+f"(d[3])
        : "r"(a0), "r"(a1), "r"(a2), "r"(a3), "r"(b0), "r"(b1));
}

// ============================================================
// Kernel 1: fused quant (bid<200) + projections (bid>=200).
// grid 1000 x 256, shared union 44KB.
// Projections store tf32-ROUNDED fp32 so attention loaders skip cvt.
// ============================================================
__global__ __launch_bounds__(256) void quant_proj_kernel(
    const float* __restrict__ x, const float* __restrict__ cb,
    float* __restrict__ outQ,
    const float* __restrict__ W0, const float* __restrict__ b0,
    const float* __restrict__ W1, const float* __restrict__ b1,
    const float* __restrict__ W2, const float* __restrict__ b2,
    const float* __restrict__ W3, const float* __restrict__ b3,
    const float* __restrict__ W4, const float* __restrict__ b4,
    const float* __restrict__ W5, const float* __restrict__ b5)
{
    __shared__ float sm[11008];
    int w = threadIdx.x >> 5, lane = threadIdx.x & 31;

    if (blockIdx.x >= 200) {
        // ---------------- projection branch ----------------
        float* xs = sm;                // 4096
        float* Ws = sm + 4096;         // 4096
        float* bs = sm + 8192;         // 64
        int bid = blockIdx.x - 200;
        int p = bid / 100;
        int rowBase = (bid % 100) * 64;

        const float* Wl[6] = {W0, W1, W2, W3, W4, W5};
        const float* bl[6] = {b0, b1, b2, b3, b4, b5};
        float* ol[6] = {g_qis, g_kis, g_vis, g_qcs, g_kcs, g_vcs};
        const float* W = Wl[p];
        float* o = ol[p];

        for (int i = threadIdx.x; i < 64 * 64; i += 256) {
            xs[i] = x[rowBase * 64 + i];
            Ws[i] = W[i];
        }
        if (threadIdx.x < 64) bs[threadIdx.x] = bl[p][threadIdx.x];
        __syncthreads();

        float a0[8], a1[8];
#pragma unroll
        for (int r = 0; r < 8; r++) { a0[r] = 0.f; a1[r] = 0.f; }
        for (int d = 0; d < 64; d++) {
            float w0 = Ws[d * 64 + lane];
            float w1 = Ws[d * 64 + lane + 32];
#pragma unroll
            for (int r = 0; r < 8; r++) {
                float xv = xs[(8 * w + r) * 64 + d];
                a0[r] = fmaf(xv, w0, a0[r]);
                a1[r] = fmaf(xv, w1, a1[r]);
            }
        }
        float bb0 = bs[lane], bb1 = bs[lane + 32];
#pragma unroll
        for (int r = 0; r < 8; r++) {
            int row = rowBase + 8 * w + r;
            o[row * 64 + lane]      = __uint_as_float(f2tf(a0[r] + bb0));
            o[row * 64 + lane + 32] = __uint_as_float(f2tf(a1[r] + bb1));
        }
        return;
    }

    // ---------------- quant branch ----------------
    float* fs = sm;                    // 32*68 = 2176
    float* cs = sm + 2176;             // 128*68 = 8704
    float* cn = sm + 10880;            // 128
    int rowBase = blockIdx.x * 32;
    for (int i = threadIdx.x; i < 32 * 64; i += 256)
        fs[(i >> 6) * 68 + (i & 63)] = x[rowBase * 64 + i];

    float bestd[4]; int besti[4];
#pragma unroll
    for (int r = 0; r < 4; r++) { bestd[r] = 3.4e38f; besti[r] = 0; }

    const float4* fs4 = (const float4*)fs;
    const float4* cs4 = (const float4*)cs;

    for (int ch = 0; ch < 4; ch++) {
        __syncthreads();
        for (int i = threadIdx.x; i < 128 * 64; i += 256)
            cs[(i >> 6) * 68 + (i & 63)] = cb[ch * 128 * 64 + i];
        __syncthreads();
        if (threadIdx.x < 128) {
            float s = 0.f;
#pragma unroll 4
            for (int q = 0; q < 16; q++) {
                float4 c = cs4[threadIdx.x * 17 + q];
                s = fmaf(c.x, c.x, s); s = fmaf(c.y, c.y, s);
                s = fmaf(c.z, c.z, s); s = fmaf(c.w, c.w, s);
            }
            cn[threadIdx.x] = s;
        }
        __syncthreads();

        float d[4][4];
#pragma unroll
        for (int r = 0; r < 4; r++)
#pragma unroll
            for (int j = 0; j < 4; j++) d[r][j] = 0.f;

#pragma unroll 4
        for (int q = 0; q < 16; q++) {
            float4 cv[4];
#pragma unroll
            for (int j = 0; j < 4; j++) cv[j] = cs4[(j * 32 + lane) * 17 + q];
#pragma unroll
            for (int r = 0; r < 4; r++) {
                float4 f = fs4[(4 * w + r) * 17 + q];
#pragma unroll
                for (int j = 0; j < 4; j++) {
                    d[r][j] = fmaf(f.x, cv[j].x, d[r][j]);
                    d[r][j] = fmaf(f.y, cv[j].y, d[r][j]);
                    d[r][j] = fmaf(f.z, cv[j].z, d[r][j]);
                    d[r][j] = fmaf(f.w, cv[j].w, d[r][j]);
                }
            }
        }
#pragma unroll
        for (int r = 0; r < 4; r++) {
#pragma unroll
            for (int j = 0; j < 4; j++) {
                int ci = j * 32 + lane;
                float dist = cn[ci] - 2.f * d[r][j];
                int idx = ch * 128 + ci;
                if (dist < bestd[r] || (dist == bestd[r] && idx < besti[r])) {
                    bestd[r] = dist; besti[r] = idx;
                }
            }
        }
    }
#pragma unroll
    for (int r = 0; r < 4; r++) {
#pragma unroll
        for (int off = 16; off > 0; off >>= 1) {
            float ob = __shfl_xor_sync(0xffffffffu, bestd[r], off);
            int   oi = __shfl_xor_sync(0xffffffffu, besti[r], off);
            if (ob < bestd[r] || (ob == bestd[r] && oi < besti[r])) {
                bestd[r] = ob; besti[r] = oi;
            }
        }
        int idx = besti[r];
        int row = rowBase + 4 * w + r;
        outQ[row * 64 + lane]      = cb[idx * 64 + lane];
        outQ[row * 64 + lane + 32] = cb[idx * 64 + lane + 32];
    }
}

// ============================================================
// Kernel 2: fused attention. bid<128: IS (one (b,d), single tile,
// 50 rows/keys padded to 64). bid>=128: CS flash split-K (as R5).
// 128 threads, 96KB dynamic smem.
// ============================================================
__global__ __launch_bounds__(128) void attn_kernel(float* __restrict__ outZ)
{
    extern __shared__ uint32_t smbuf[];
    int t = threadIdx.x;
    int wm = t >> 5, lane = t & 31;
    int g = lane >> 2, c4 = lane & 3;

    if (blockIdx.x < 128) {
        // ================= IS attention =================
        uint32_t* Qs = smbuf;
        uint32_t* Ks = smbuf + 4096;
        uint32_t* Vs = smbuf + 8192;
        uint32_t* Ps = smbuf + 12288;
        int base = blockIdx.x * 50;

        const uint4* Qg = (const uint4*)(g_kis + base * 64);
        const uint4* Kg = (const uint4*)(g_qis + base * 64);
        const uint4* Vg = (const uint4*)(g_vis + base * 64);
        for (int i = t; i < 1024; i += 128) {
            int row = i >> 4, j = i & 15;
            *(uint4*)(Qs + row * 64 + 4 * (j ^ (row & 7)))       = Qg[i];
            *(uint4*)(Ks + row * 64 + 4 * (j ^ (row & 7)))       = Kg[i];
            *(uint4*)(Vs + row * 64 + 4 * (j ^ (2 * (row & 3)))) = Vg[i];
        }
        __syncthreads();

        int rL = (wm * 16 + g) * 64;
        float S[8][4];
#pragma unroll
        for (int n = 0; n < 8; n++)
#pragma unroll
            for (int j = 0; j < 4; j++) S[n][j] = 0.f;

#pragma unroll
        for (int k0 = 0; k0 < 8; k0++) {
            int ch0 = 4 * ((2 * k0) ^ g);
            int ch1 = 4 * ((2 * k0 + 1) ^ g);
            uint32_t a0 = Qs[rL + ch0 + c4];
            uint32_t a1 = Qs[rL + 512 + ch0 + c4];
            uint32_t a2 = Qs[rL + ch1 + c4];
            uint32_t a3 = Qs[rL + 512 + ch1 + c4];
#pragma unroll
            for (int n0 = 0; n0 < 8; n0++) {
                int key = n0 * 8 + g;
                uint32_t b0 = Ks[key * 64 + ch0 + c4];
                uint32_t b1 = Ks[key * 64 + ch1 + c4];
                mma_tf32(S[n0], a0, a1, a2, a3, b0, b1);
            }
        }

        // mask cols >= 50, single-pass softmax
        float rmA = -1e30f, rmB = -1e30f;
#pragma unroll
        for (int n0 = 0; n0 < 8; n0++) {
            int col0 = n0 * 8 + 2 * c4;
            if (col0 >= 50)     { S[n0][0] = -1e30f; S[n0][2] = -1e30f; }
            if (col0 + 1 >= 50) { S[n0][1] = -1e30f; S[n0][3] = -1e30f; }
            rmA = fmaxf(rmA, fmaxf(S[n0][0], S[n0][1]));
            rmB = fmaxf(rmB, fmaxf(S[n0][2], S[n0][3]));
        }
        rmA = fmaxf(rmA, __shfl_xor_sync(0xffffffffu, rmA, 1));
        rmA = fmaxf(rmA, __shfl_xor_sync(0xffffffffu, rmA, 2));
        rmB = fmaxf(rmB, __shfl_xor_sync(0xffffffffu, rmB, 1));
        rmB = fmaxf(rmB, __shfl_xor_sync(0xffffffffu, rmB, 2));

        float lsA = 0.f, lsB = 0.f;
#pragma unroll
        for (int n0 = 0; n0 < 8; n0++) {
            float pA0 = __expf(S[n0][0] - rmA);
            float pA1 = __expf(S[n0][1] - rmA);
            float pB0 = __expf(S[n0][2] - rmB);
            float pB1 = __expf(S[n0][3] - rmB);
            lsA += pA0 + pA1;
            lsB += pB0 + pB1;
            int chp = 4 * ((2 * n0 + (c4 >> 1)) ^ g) + ((2 * c4) & 3);
            *(uint2*)(Ps + rL + chp)       = make_uint2(f2tf(pA0), f2tf(pA1));
            *(uint2*)(Ps + rL + 512 + chp) = make_uint2(f2tf(pB0), f2tf(pB1));
        }
        lsA += __shfl_xor_sync(0xffffffffu, lsA, 1);
        lsA += __shfl_xor_sync(0xffffffffu, lsA, 2);
        lsB += __shfl_xor_sync(0xffffffffu, lsB, 1);
        lsB += __shfl_xor_sync(0xffffffffu, lsB, 2);
        __syncwarp();

        float O[8][4];
#pragma unroll
        for (int n = 0; n < 8; n++)
#pragma unroll
            for (int j = 0; j < 4; j++) O[n][j] = 0.f;

#pragma unroll
        for (int k0 = 0; k0 < 8; k0++) {
            int ch0 = 4 * ((2 * k0) ^ g);
            int ch1 = 4 * ((2 * k0 + 1) ^ g);
            uint32_t a0 = Ps[rL + ch0 + c4];
            uint32_t a1 = Ps[rL + 512 + ch0 + c4];
            uint32_t a2 = Ps[rL + ch1 + c4];
            uint32_t a3 = Ps[rL + 512 + ch1 + c4];
            int ky0 = (k0 * 8 + c4) * 64;
            int ky1 = ky0 + 256;
            int sw = 2 * c4;
#pragma unroll
            for (int n0 = 0; n0 < 8; n0++) {
                int ch = 4 * ((2 * n0 + (g >> 2)) ^ sw) + (g & 3);
                uint32_t b0 = Vs[ky0 + ch];
                uint32_t b1 = Vs[ky1 + ch];
                mma_tf32(O[n0], a0, a1, a2, a3, b0, b1);
            }
        }

        float invA = 1.f / lsA, invB = 1.f / lsB;
        int r0 = wm * 16 + g;
#pragma unroll
        for (int n0 = 0; n0 < 8; n0++) {
            int col = n0 * 8 + 2 * c4;
            if (r0 < 50)
                *(float2*)(outZ + (base + r0) * 64 + col) =
                    make_float2(O[n0][0] * invA, O[n0][1] * invA);
            if (r0 + 8 < 50)
                *(float2*)(outZ + (base + r0 + 8) * 64 + col) =
                    make_float2(O[n0][2] * invB, O[n0][3] * invB);
        }
        return;
    }

    // ================= CS attention (flash + split-K) =================
    uint32_t* Qs = smbuf;            // 8192 words
    uint32_t* Ks = smbuf + 8192;     // 4096
    uint32_t* Vs = smbuf + 12288;    // 4096
    uint32_t* Ps = smbuf + 16384;    // 8192

    int bid = blockIdx.x - 128;
    int qt = bid / NSPLIT, sp = bid % NSPLIT;
    int qBase = qt * 128;

    {
        const uint4* Qg = (const uint4*)(g_kcs + qBase * 64);
        for (int i = t; i < 2048; i += 128) {
            int row = i >> 4, j = i & 15;
            *(uint4*)(Qs + row * 64 + 4 * (j ^ (row & 7))) = Qg[i];
        }
    }

    float S[2][8][4];
    float O[2][8][4];
#pragma unroll
    for (int b = 0; b < 2; b++)
#pragma unroll
        for (int n = 0; n < 8; n++)
#pragma unroll
            for (int j = 0; j < 4; j++) O[b][n][j] = 0.f;

    float mv[4], lv[4];
    int qsamp[4];
#pragma unroll
    for (int s = 0; s < 4; s++) {
        mv[s] = -1e30f; lv[s] = 0.f;
        int row = qBase + wm * 32 + (s >> 1) * 16 + (s & 1) * 8 + g;
        qsamp[s] = row / GROUP;
    }

    int ktStart = sp * TILES_PER_SPLIT;
    int ktEnd = ktStart + TILES_PER_SPLIT;
    if (ktEnd > 100) ktEnd = 100;

    for (int kt = ktStart; kt < ktEnd; kt++) {
        __syncthreads();
        int kBase = kt * 64;
        {
            const uint4* Kg = (const uint4*)(g_qcs + kBase * 64);
            const uint4* Vg = (const uint4*)(g_vcs + kBase * 64);
            for (int i = t; i < 1024; i += 128) {
                int key = i >> 4, j = i & 15;
                *(uint4*)(Ks + key * 64 + 4 * (j ^ (key & 7)))       = Kg[i];
                *(uint4*)(Vs + key * 64 + 4 * (j ^ (2 * (key & 3)))) = Vg[i];
            }
        }
        __syncthreads();

#pragma unroll
        for (int b = 0; b < 2; b++)
#pragma unroll
            for (int n = 0; n < 8; n++)
#pragma unroll
                for (int j = 0; j < 4; j++) S[b][n][j] = 0.f;

#pragma unroll
        for (int k0 = 0; k0 < 8; k0++) {
            int ch0 = 4 * ((2 * k0) ^ g);
            int ch1 = 4 * ((2 * k0 + 1) ^ g);
            uint32_t a[2][4];
#pragma unroll
            for (int b = 0; b < 2; b++) {
                int rL = (wm * 32 + b * 16 + g) * 64;
                a[b][0] = Qs[rL + ch0 + c4];
                a[b][1] = Qs[rL + 512 + ch0 + c4];
                a[b][2] = Qs[rL + ch1 + c4];
                a[b][3] = Qs[rL + 512 + ch1 + c4];
            }
#pragma unroll
            for (int n0 = 0; n0 < 8; n0++) {
                int key = n0 * 8 + g;
                uint32_t b0 = Ks[key * 64 + ch0 + c4];
                uint32_t b1 = Ks[key * 64 + ch1 + c4];
                mma_tf32(S[0][n0], a[0][0], a[0][1], a[0][2], a[0][3], b0, b1);
                mma_tf32(S[1][n0], a[1][0], a[1][1], a[1][2], a[1][3], b0, b1);
            }
        }

        float rm[4] = {-1e30f, -1e30f, -1e30f, -1e30f};
#pragma unroll
        for (int n0 = 0; n0 < 8; n0++) {
            int col0 = kBase + n0 * 8 + 2 * c4;
            int cs0 = col0 / GROUP, cs1 = (col0 + 1) / GROUP;
#pragma unroll
            for (int s = 0; s < 4; s++) {
                int b = s >> 1, h = s & 1;
                if (cs0 == qsamp[s]) S[b][n0][2 * h]     = -1e30f;
                if (cs1 == qsamp[s]) S[b][n0][2 * h + 1] = -1e30f;
                rm[s] = fmaxf(rm[s], fmaxf(S[b][n0][2 * h], S[b][n0][2 * h + 1]));
            }
        }
        float corr[4];
#pragma unroll
        for (int s = 0; s < 4; s++) {
            rm[s] = fmaxf(rm[s], __shfl_xor_sync(0xffffffffu, rm[s], 1));
            rm[s] = fmaxf(rm[s], __shfl_xor_sync(0xffffffffu, rm[s], 2));
            float mn = fmaxf(mv[s], rm[s]);
            corr[s] = __expf(mv[s] - mn);
            mv[s] = mn;
        }
        float ls[4] = {0.f, 0.f, 0.f, 0.f};
#pragma unroll
        for (int n0 = 0; n0 < 8; n0++) {
            int chp = 4 * ((2 * n0 + (c4 >> 1)) ^ g) + ((2 * c4) & 3);
#pragma unroll
            for (int s = 0; s < 4; s++) {
                int b = s >> 1, h = s & 1;
                float p0 = __expf(S[b][n0][2 * h]     - mv[s]);
                float p1 = __expf(S[b][n0][2 * h + 1] - mv[s]);
                ls[s] += p0 + p1;
                int row = wm * 32 + b * 16 + h * 8 + g;
                *(uint2*)(Ps + row * 64 + chp) = make_uint2(f2tf(p0), f2tf(p1));
            }
        }
#pragma unroll
        for (int s = 0; s < 4; s++) {
            ls[s] += __shfl_xor_sync(0xffffffffu, ls[s], 1);
            ls[s] += __shfl_xor_sync(0xffffffffu, ls[s], 2);
            lv[s] = lv[s] * corr[s] + ls[s];
            int b = s >> 1, h = s & 1;
#pragma unroll
            for (int n0 = 0; n0 < 8; n0++) {
                O[b][n0][2 * h]     *= corr[s];
                O[b][n0][2 * h + 1] *= corr[s];
            }
        }
        __syncwarp();

#pragma unroll
        for (int k0 = 0; k0 < 8; k0++) {
            int ch0 = 4 * ((2 * k0) ^ g);
            int ch1 = 4 * ((2 * k0 + 1) ^ g);
            uint32_t a[2][4];
#pragma unroll
            for (int b = 0; b < 2; b++) {
                int rL = (wm * 32 + b * 16 + g) * 64;
                a[b][0] = Ps[rL + ch0 + c4];
                a[b][1] = Ps[rL + 512 + ch0 + c4];
                a[b][2] = Ps[rL + ch1 + c4];
                a[b][3] = Ps[rL + 512 + ch1 + c4];
            }
            int ky0 = (k0 * 8 + c4) * 64;
            int ky1 = ky0 + 256;
            int sw = 2 * c4;
#pragma unroll
            for (int n0 = 0; n0 < 8; n0++) {
                int ch = 4 * ((2 * n0 + (g >> 2)) ^ sw) + (g & 3);
                uint32_t b0 = Vs[ky0 + ch];
                uint32_t b1 = Vs[ky1 + ch];
                mma_tf32(O[0][n0], a[0][0], a[0][1], a[0][2], a[0][3], b0, b1);
                mma_tf32(O[1][n0], a[1][0], a[1][1], a[1][2], a[1][3], b0, b1);
            }
        }
    }

    float* Op = g_Opart[sp];
#pragma unroll
    for (int b = 0; b < 2; b++) {
        int rowA = qBase + wm * 32 + b * 16 + g;
#pragma unroll
        for (int n0 = 0; n0 < 8; n0++) {
            int col = n0 * 8 + 2 * c4;
            *(float2*)(Op + rowA * 64 + col)       = make_float2(O[b][n0][0], O[b][n0][1]);
            *(float2*)(Op + (rowA + 8) * 64 + col) = make_float2(O[b][n0][2], O[b][n0][3]);
        }
    }
    if (c4 == 0) {
#pragma unroll
        for (int s = 0; s < 4; s++) {
            int row = qBase + wm * 32 + (s >> 1) * 16 + (s & 1) * 8 + g;
            g_mpart[sp][row] = mv[s];
            g_lpart[sp][row] = lv[s];
        }
    }
}

// ============================================================
// Kernel 3: combine split-K partials.
// ============================================================
__global__ __launch_bounds__(256) void cs_combine_kernel(float* __restrict__ outX)
{
    int gidx = blockIdx.x * 256 + threadIdx.x;
    int row = gidx >> 4;
    int e4 = gidx & 15;
    if (row >= N_ROWS) return;

    float m[NSPLIT];
    float M = -3.4e38f;
#pragma unroll
    for (int s = 0; s < NSPLIT; s++) { m[s] = g_mpart[s][row]; M = fmaxf(M, m[s]); }
    float wgt[NSPLIT];
    float denom = 0.f;
#pragma unroll
    for (int s = 0; s < NSPLIT; s++) {
        wgt[s] = __expf(m[s] - M);
        denom += wgt[s] * g_lpart[s][row];
    }
    float inv = 1.f / denom;

    float4 o = {0.f, 0.f, 0.f, 0.f};
#pragma unroll
    for (int s = 0; s < NSPLIT; s++) {
        float4 a = ((const float4*)g_Opart[s])[row * 16 + e4];
        o.x = fmaf(a.x, wgt[s], o.x);
        o.y = fmaf(a.y, wgt[s], o.y);
        o.z = fmaf(a.z, wgt[s], o.z);
        o.w = fmaf(a.w, wgt[s], o.w);
    }
    o.x *= inv; o.y *= inv; o.z *= inv; o.w *= inv;
    ((float4*)outX)[row * 16 + e4] = o;
}

// ============================================================
extern "C" void kernel_launch(void* const* d_in, const int* in_sizes, int n_in,
                              void* d_out, int out_size)
{
    const float* x    = (const float*)d_in[0];
    const float* cb   = (const float*)d_in[1];
    const float* Wqis = (const float*)d_in[2];  const float* bqis = (const float*)d_in[3];
    const float* Wkis = (const float*)d_in[4];  const float* bkis = (const float*)d_in[5];
    const float* Wvis = (const float*)d_in[6];  const float* bvis = (const float*)d_in[7];
    const float* Wqcs = (const float*)d_in[8];  const float* bqcs = (const float*)d_in[9];
    const float* Wkcs = (const float*)d_in[10]; const float* bkcs = (const float*)d_in[11];
    const float* Wvcs = (const float*)d_in[12]; const float* bvcs = (const float*)d_in[13];
    float* out = (float*)d_out;

    cudaFuncSetAttribute(attn_kernel,
                         cudaFuncAttributeMaxDynamicSharedMemorySize, 98304);

    quant_proj_kernel<<<800, 256>>>(x, cb, out,
                                    Wqis, bqis, Wkis, bkis, Wvis, bvis,
                                    Wqcs, bqcs, Wkcs, bkcs, Wvcs, bvcs);
    attn_kernel<<<128 + 50 * NSPLIT, 128, 98304>>>(out + N_ROWS * DIMV);
    cs_combine_kernel<<<(N_ROWS * 16 + 255) / 256, 256>>>(out + 2 * N_ROWS * DIMV);
}

// round 7
// speedup vs baseline: 5.6638x; 1.0298x over previous
#include <cuda_runtime.h>
#include <cstdint>

#define N_ROWS 6400
#define DIMV 64
#define NUM_EMB 512
#define GROUP 100
#define NSPLIT 6
#define TILES_PER_SPLIT 17   // 5*17 + 15 = 100 key tiles of 64

// ---- scratch (no cudaMalloc allowed); +1024 pad so 64-row tile reads
// starting at row 6350 never go OOB ----
__device__ float g_qis[N_ROWS * DIMV + 1024];
__device__ float g_kis[N_ROWS * DIMV + 1024];
__device__ float g_vis[N_ROWS * DIMV + 1024];
__device__ float g_qcs[N_ROWS * DIMV + 1024];
__device__ float g_kcs[N_ROWS * DIMV + 1024];
__device__ float g_vcs[N_ROWS * DIMV + 1024];
__device__ float g_Opart[NSPLIT][N_ROWS * DIMV];
__device__ float g_mpart[NSPLIT][N_ROWS];
__device__ float g_lpart[NSPLIT][N_ROWS];

__device__ __forceinline__ uint32_t f2tf(float f) {
    uint32_t u;
    asm("cvt.rna.tf32.f32 %0, %1;" : "=r"(u) : "f"(f));
    return u;
}

__device__ __forceinline__ void mma_tf32(
    float* d,
    uint32_t a0, uint32_t a1, uint32_t a2, uint32_t a3,
    uint32_t b0, uint32_t b1)
{
    asm volatile(
        "mma.sync.aligned.m16n8k8.row.col.f32.tf32.tf32.f32 "
        "{%0,%1,%2,%3},{%4,%5,%6,%7},{%8,%9},{%0,%1,%2,%3};\n"
        : "+f"(d[0]), "+f"(d[1]), "+f"(d[2]), "+f"(d[3])
        : "r"(a0), "r"(a1), "r"(a2), "r"(a3), "r"(b0), "r"(b1));
}

// ============================================================
// Kernel 1: six projections, one (proj, 64-row block) per CTA.
// grid 600 x 256. Stores tf32-ROUNDED fp32 for the attention MMAs.
// ============================================================
__global__ __launch_bounds__(256) void proj_kernel(
    const float* __restrict__ x,
    const float* __restrict__ W0, const float* __restrict__ b0,
    const float* __restrict__ W1, const float* __restrict__ b1,
    const float* __restrict__ W2, const float* __restrict__ b2,
    const float* __restrict__ W3, const float* __restrict__ b3,
    const float* __restrict__ W4, const float* __restrict__ b4,
    const float* __restrict__ W5, const float* __restrict__ b5)
{
    __shared__ float xs[64 * 64];
    __shared__ float Ws[64 * 64];
    __shared__ float bs[64];
    int p = blockIdx.x / 100;
    int rowBase = (blockIdx.x % 100) * 64;

    const float* Wl[6] = {W0, W1, W2, W3, W4, W5};
    const float* bl[6] = {b0, b1, b2, b3, b4, b5};
    float* ol[6] = {g_qis, g_kis, g_vis, g_qcs, g_kcs, g_vcs};
    const float* W = Wl[p];
    float* o = ol[p];

    for (int i = threadIdx.x; i < 64 * 64; i += 256) {
        xs[i] = x[rowBase * 64 + i];
        Ws[i] = W[i];
    }
    if (threadIdx.x < 64) bs[threadIdx.x] = bl[p][threadIdx.x];
    __syncthreads();

    int w = threadIdx.x >> 5, lane = threadIdx.x & 31;
    float a0[8], a1[8];
#pragma unroll
    for (int r = 0; r < 8; r++) { a0[r] = 0.f; a1[r] = 0.f; }
    for (int d = 0; d < 64; d++) {
        float w0 = Ws[d * 64 + lane];
        float w1 = Ws[d * 64 + lane + 32];
#pragma unroll
        for (int r = 0; r < 8; r++) {
            float xv = xs[(8 * w + r) * 64 + d];
            a0[r] = fmaf(xv, w0, a0[r]);
            a1[r] = fmaf(xv, w1, a1[r]);
        }
    }
    float bb0 = bs[lane], bb1 = bs[lane + 32];
#pragma unroll
    for (int r = 0; r < 8; r++) {
        int row = rowBase + 8 * w + r;
        o[row * 64 + lane]      = __uint_as_float(f2tf(a0[r] + bb0));
        o[row * 64 + lane + 32] = __uint_as_float(f2tf(a1[r] + bb1));
    }
}

// ============================================================
// Kernel 2: fused attention + quantization. 128 threads, 96KB dyn smem.
//   bid 0..299   : CS flash split-K (tf32 MMA)
//   bid 300..427 : IS attention (tf32 MMA, single 64-pad tile)
//   bid 428..527 : vector quantization (3-term tf32 MMA + argmin)
// ============================================================
__global__ __launch_bounds__(128) void attn_kernel(
    const float* __restrict__ x, const float* __restrict__ cb,
    float* __restrict__ out)
{
    extern __shared__ uint32_t smbuf[];
    int t = threadIdx.x;
    int wm = t >> 5, lane = t & 31;
    int g = lane >> 2, c4 = lane & 3;

    if (blockIdx.x >= 428) {
        // ================= quantization =================
        uint32_t* Fh = smbuf;            // 4096
        uint32_t* Fl = smbuf + 4096;     // 4096
        uint32_t* Ch = smbuf + 8192;     // 4096
        uint32_t* Cl = smbuf + 12288;    // 4096
        float* cns = (float*)(smbuf + 16384);  // 64

        int rBase = (blockIdx.x - 428) * 64;
        const float4* Fg = (const float4*)(x + rBase * 64);
        for (int i = t; i < 1024; i += 128) {
            int row = i >> 4, j = i & 15;
            float4 f = Fg[i];
            uint32_t h0 = f2tf(f.x), h1 = f2tf(f.y), h2 = f2tf(f.z), h3 = f2tf(f.w);
            int ad = row * 64 + 4 * (j ^ (row & 7));
            *(uint4*)(Fh + ad) = make_uint4(h0, h1, h2, h3);
            *(uint4*)(Fl + ad) = make_uint4(
                f2tf(f.x - __uint_as_float(h0)), f2tf(f.y - __uint_as_float(h1)),
                f2tf(f.z - __uint_as_float(h2)), f2tf(f.w - __uint_as_float(h3)));
        }

        float bA = 3.4e38f, bB = 3.4e38f;
        int iA = 0, iB = 0;
        int rL = (wm * 16 + g) * 64;

        for (int ct = 0; ct < 8; ct++) {
            __syncthreads();
            const float4* Cg = (const float4*)(cb + ct * 64 * 64);
            for (int i = t; i < 1024; i += 128) {
                int code = i >> 4, j = i & 15;
                float4 f = Cg[i];
                uint32_t h0 = f2tf(f.x), h1 = f2tf(f.y), h2 = f2tf(f.z), h3 = f2tf(f.w);
                int ad = code * 64 + 4 * (j ^ (code & 7));
                *(uint4*)(Ch + ad) = make_uint4(h0, h1, h2, h3);
                *(uint4*)(Cl + ad) = make_uint4(
                    f2tf(f.x - __uint_as_float(h0)), f2tf(f.y - __uint_as_float(h1)),
                    f2tf(f.z - __uint_as_float(h2)), f2tf(f.w - __uint_as_float(h3)));
            }
            __syncthreads();
            if (t < 64) {
                float s = 0.f;
#pragma unroll
                for (int j = 0; j < 16; j++) {
                    int ad = t * 64 + 4 * (j ^ (t & 7));
                    uint4 h = *(uint4*)(Ch + ad);
                    uint4 l = *(uint4*)(Cl + ad);
                    float v;
                    v = __uint_as_float(h.x) + __uint_as_float(l.x); s = fmaf(v, v, s);
                    v = __uint_as_float(h.y) + __uint_as_float(l.y); s = fmaf(v, v, s);
                    v = __uint_as_float(h.z) + __uint_as_float(l.z); s = fmaf(v, v, s);
                    v = __uint_as_float(h.w) + __uint_as_float(l.w); s = fmaf(v, v, s);
                }
                cns[t] = s;
            }
            __syncthreads();

            float S[8][4];
#pragma unroll
            for (int n = 0; n < 8; n++)
#pragma unroll
                for (int j = 0; j < 4; j++) S[n][j] = 0.f;

#pragma unroll
            for (int k0 = 0; k0 < 8; k0++) {
                int ch0 = 4 * ((2 * k0) ^ g);
                int ch1 = 4 * ((2 * k0 + 1) ^ g);
                uint32_t ah0 = Fh[rL + ch0 + c4], ah1 = Fh[rL + 512 + ch0 + c4];
                uint32_t ah2 = Fh[rL + ch1 + c4], ah3 = Fh[rL + 512 + ch1 + c4];
                uint32_t al0 = Fl[rL + ch0 + c4], al1 = Fl[rL + 512 + ch0 + c4];
                uint32_t al2 = Fl[rL + ch1 + c4], al3 = Fl[rL + 512 + ch1 + c4];
#pragma unroll
                for (int n0 = 0; n0 < 8; n0++) {
                    int key = n0 * 8 + g;
                    uint32_t bh0 = Ch[key * 64 + ch0 + c4];
                    uint32_t bh1 = Ch[key * 64 + ch1 + c4];
                    uint32_t bl0 = Cl[key * 64 + ch0 + c4];
                    uint32_t bl1 = Cl[key * 64 + ch1 + c4];
                    mma_tf32(S[n0], ah0, ah1, ah2, ah3, bh0, bh1);
                    mma_tf32(S[n0], ah0, ah1, ah2, ah3, bl0, bl1);
                    mma_tf32(S[n0], al0, al1, al2, al3, bh0, bh1);
                }
            }

#pragma unroll
            for (int n0 = 0; n0 < 8; n0++) {
                int c0 = n0 * 8 + 2 * c4;
                float cn0 = cns[c0], cn1 = cns[c0 + 1];
                int gi = ct * 64 + c0;
                float d;
                d = cn0 - 2.f * S[n0][0];
                if (d < bA || (d == bA && gi < iA)) { bA = d; iA = gi; }
                d = cn1 - 2.f * S[n0][1];
                if (d < bA || (d == bA && gi + 1 < iA)) { bA = d; iA = gi + 1; }
                d = cn0 - 2.f * S[n0][2];
                if (d < bB || (d == bB && gi < iB)) { bB = d; iB = gi; }
                d = cn1 - 2.f * S[n0][3];
                if (d < bB || (d == bB && gi + 1 < iB)) { bB = d; iB = gi + 1; }
            }
        }
#pragma unroll
        for (int off = 1; off <= 2; off <<= 1) {
            float ob; int oi;
            ob = __shfl_xor_sync(0xffffffffu, bA, off);
            oi = __shfl_xor_sync(0xffffffffu, iA, off);
            if (ob < bA || (ob == bA && oi < iA)) { bA = ob; iA = oi; }
            ob = __shfl_xor_sync(0xffffffffu, bB, off);
            oi = __shfl_xor_sync(0xffffffffu, iB, off);
            if (ob < bB || (ob == bB && oi < iB)) { bB = ob; iB = oi; }
        }
        int rA = rBase + wm * 16 + g;
        const float4* cbA = (const float4*)(cb + iA * 64);
        const float4* cbB = (const float4*)(cb + iB * 64);
        float4* oA = (float4*)(out + rA * 64);
        float4* oB = (float4*)(out + (rA + 8) * 64);
#pragma unroll
        for (int j = 0; j < 4; j++) {
            oA[c4 * 4 + j] = cbA[c4 * 4 + j];
            oB[c4 * 4 + j] = cbB[c4 * 4 + j];
        }
        return;
    }

    float* outZ = out + N_ROWS * DIMV;

    if (blockIdx.x >= 300) {
        // ================= IS attention =================
        uint32_t* Qs = smbuf;
        uint32_t* Ks = smbuf + 4096;
        uint32_t* Vs = smbuf + 8192;
        uint32_t* Ps = smbuf + 12288;
        int base = (blockIdx.x - 300) * 50;

        const uint4* Qg = (const uint4*)(g_kis + base * 64);
        const uint4* Kg = (const uint4*)(g_qis + base * 64);
        const uint4* Vg = (const uint4*)(g_vis + base * 64);
        for (int i = t; i < 1024; i += 128) {
            int row = i >> 4, j = i & 15;
            *(uint4*)(Qs + row * 64 + 4 * (j ^ (row & 7)))       = Qg[i];
            *(uint4*)(Ks + row * 64 + 4 * (j ^ (row & 7)))       = Kg[i];
            *(uint4*)(Vs + row * 64 + 4 * (j ^ (2 * (row & 3)))) = Vg[i];
        }
        __syncthreads();

        int rL = (wm * 16 + g) * 64;
        float S[8][4];
#pragma unroll
        for (int n = 0; n < 8; n++)
#pragma unroll
            for (int j = 0; j < 4; j++) S[n][j] = 0.f;

#pragma unroll
        for (int k0 = 0; k0 < 8; k0++) {
            int ch0 = 4 * ((2 * k0) ^ g);
            int ch1 = 4 * ((2 * k0 + 1) ^ g);
            uint32_t a0 = Qs[rL + ch0 + c4];
            uint32_t a1 = Qs[rL + 512 + ch0 + c4];
            uint32_t a2 = Qs[rL + ch1 + c4];
            uint32_t a3 = Qs[rL + 512 + ch1 + c4];
#pragma unroll
            for (int n0 = 0; n0 < 8; n0++) {
                int key = n0 * 8 + g;
                uint32_t b0 = Ks[key * 64 + ch0 + c4];
                uint32_t b1 = Ks[key * 64 + ch1 + c4];
                mma_tf32(S[n0], a0, a1, a2, a3, b0, b1);
            }
        }

        float rmA = -1e30f, rmB = -1e30f;
#pragma unroll
        for (int n0 = 0; n0 < 8; n0++) {
            int col0 = n0 * 8 + 2 * c4;
            if (col0 >= 50)     { S[n0][0] = -1e30f; S[n0][2] = -1e30f; }
            if (col0 + 1 >= 50) { S[n0][1] = -1e30f; S[n0][3] = -1e30f; }
            rmA = fmaxf(rmA, fmaxf(S[n0][0], S[n0][1]));
            rmB = fmaxf(rmB, fmaxf(S[n0][2], S[n0][3]));
        }
        rmA = fmaxf(rmA, __shfl_xor_sync(0xffffffffu, rmA, 1));
        rmA = fmaxf(rmA, __shfl_xor_sync(0xffffffffu, rmA, 2));
        rmB = fmaxf(rmB, __shfl_xor_sync(0xffffffffu, rmB, 1));
        rmB = fmaxf(rmB, __shfl_xor_sync(0xffffffffu, rmB, 2));

        float lsA = 0.f, lsB = 0.f;
#pragma unroll
        for (int n0 = 0; n0 < 8; n0++) {
            float pA0 = __expf(S[n0][0] - rmA);
            float pA1 = __expf(S[n0][1] - rmA);
            float pB0 = __expf(S[n0][2] - rmB);
            float pB1 = __expf(S[n0][3] - rmB);
            lsA += pA0 + pA1;
            lsB += pB0 + pB1;
            int chp = 4 * ((2 * n0 + (c4 >> 1)) ^ g) + ((2 * c4) & 3);
            *(uint2*)(Ps + rL + chp)       = make_uint2(f2tf(pA0), f2tf(pA1));
            *(uint2*)(Ps + rL + 512 + chp) = make_uint2(f2tf(pB0), f2tf(pB1));
        }
        lsA += __shfl_xor_sync(0xffffffffu, lsA, 1);
        lsA += __shfl_xor_sync(0xffffffffu, lsA, 2);
        lsB += __shfl_xor_sync(0xffffffffu, lsB, 1);
        lsB += __shfl_xor_sync(0xffffffffu, lsB, 2);
        __syncwarp();

        float O[8][4];
#pragma unroll
        for (int n = 0; n < 8; n++)
#pragma unroll
            for (int j = 0; j < 4; j++) O[n][j] = 0.f;

#pragma unroll
        for (int k0 = 0; k0 < 8; k0++) {
            int ch0 = 4 * ((2 * k0) ^ g);
            int ch1 = 4 * ((2 * k0 + 1) ^ g);
            uint32_t a0 = Ps[rL + ch0 + c4];
            uint32_t a1 = Ps[rL + 512 + ch0 + c4];
            uint32_t a2 = Ps[rL + ch1 + c4];
            uint32_t a3 = Ps[rL + 512 + ch1 + c4];
            int ky0 = (k0 * 8 + c4) * 64;
            int ky1 = ky0 + 256;
            int sw = 2 * c4;
#pragma unroll
            for (int n0 = 0; n0 < 8; n0++) {
                int ch = 4 * ((2 * n0 + (g >> 2)) ^ sw) + (g & 3);
                uint32_t b0 = Vs[ky0 + ch];
                uint32_t b1 = Vs[ky1 + ch];
                mma_tf32(O[n0], a0, a1, a2, a3, b0, b1);
            }
        }

        float invA = 1.f / lsA, invB = 1.f / lsB;
        int r0 = wm * 16 + g;
#pragma unroll
        for (int n0 = 0; n0 < 8; n0++) {
            int col = n0 * 8 + 2 * c4;
            if (r0 < 50)
                *(float2*)(outZ + (base + r0) * 64 + col) =
                    make_float2(O[n0][0] * invA, O[n0][1] * invA);
            if (r0 + 8 < 50)
                *(float2*)(outZ + (base + r0 + 8) * 64 + col) =
                    make_float2(O[n0][2] * invB, O[n0][3] * invB);
        }
        return;
    }

    // ================= CS attention (flash + split-K) =================
    uint32_t* Qs = smbuf;            // 8192 words
    uint32_t* Ks = smbuf + 8192;     // 4096
    uint32_t* Vs = smbuf + 12288;    // 4096
    uint32_t* Ps = smbuf + 16384;    // 8192

    int bid = blockIdx.x;
    int qt = bid / NSPLIT, sp = bid % NSPLIT;
    int qBase = qt * 128;

    {
        const uint4* Qg = (const uint4*)(g_kcs + qBase * 64);
        for (int i = t; i < 2048; i += 128) {
            int row = i >> 4, j = i & 15;
            *(uint4*)(Qs + row * 64 + 4 * (j ^ (row & 7))) = Qg[i];
        }
    }

    float S[2][8][4];
    float O[2][8][4];
#pragma unroll
    for (int b = 0; b < 2; b++)
#pragma unroll
        for (int n = 0; n < 8; n++)
#pragma unroll
            for (int j = 0; j < 4; j++) O[b][n][j] = 0.f;

    float mv[4], lv[4];
    int qsamp[4];
#pragma unroll
    for (int s = 0; s < 4; s++) {
        mv[s] = -1e30f; lv[s] = 0.f;
        int row = qBase + wm * 32 + (s >> 1) * 16 + (s & 1) * 8 + g;
        qsamp[s] = row / GROUP;
    }

    int ktStart = sp * TILES_PER_SPLIT;
    int ktEnd = ktStart + TILES_PER_SPLIT;
    if (ktEnd > 100) ktEnd = 100;

    for (int kt = ktStart; kt < ktEnd; kt++) {
        __syncthreads();
        int kBase = kt * 64;
        {
            const uint4* Kg = (const uint4*)(g_qcs + kBase * 64);
            const uint4* Vg = (const uint4*)(g_vcs + kBase * 64);
            for (int i = t; i < 1024; i += 128) {
                int key = i >> 4, j = i & 15;
                *(uint4*)(Ks + key * 64 + 4 * (j ^ (key & 7)))       = Kg[i];
                *(uint4*)(Vs + key * 64 + 4 * (j ^ (2 * (key & 3)))) = Vg[i];
            }
        }
        __syncthreads();

#pragma unroll
        for (int b = 0; b < 2; b++)
#pragma unroll
            for (int n = 0; n < 8; n++)
#pragma unroll
                for (int j = 0; j < 4; j++) S[b][n][j] = 0.f;

#pragma unroll
        for (int k0 = 0; k0 < 8; k0++) {
            int ch0 = 4 * ((2 * k0) ^ g);
            int ch1 = 4 * ((2 * k0 + 1) ^ g);
            uint32_t a[2][4];
#pragma unroll
            for (int b = 0; b < 2; b++) {
                int rL = (wm * 32 + b * 16 + g) * 64;
                a[b][0] = Qs[rL + ch0 + c4];
                a[b][1] = Qs[rL + 512 + ch0 + c4];
                a[b][2] = Qs[rL + ch1 + c4];
                a[b][3] = Qs[rL + 512 + ch1 + c4];
            }
#pragma unroll
            for (int n0 = 0; n0 < 8; n0++) {
                int key = n0 * 8 + g;
                uint32_t b0 = Ks[key * 64 + ch0 + c4];
                uint32_t b1 = Ks[key * 64 + ch1 + c4];
                mma_tf32(S[0][n0], a[0][0], a[0][1], a[0][2], a[0][3], b0, b1);
                mma_tf32(S[1][n0], a[1][0], a[1][1], a[1][2], a[1][3], b0, b1);
            }
        }

        float rm[4] = {-1e30f, -1e30f, -1e30f, -1e30f};
#pragma unroll
        for (int n0 = 0; n0 < 8; n0++) {
            int col0 = kBase + n0 * 8 + 2 * c4;
            int cs0 = col0 / GROUP, cs1 = (col0 + 1) / GROUP;
#pragma unroll
            for (int s = 0; s < 4; s++) {
                int b = s >> 1, h = s & 1;
                if (cs0 == qsamp[s]) S[b][n0][2 * h]     = -1e30f;
                if (cs1 == qsamp[s]) S[b][n0][2 * h + 1] = -1e30f;
                rm[s] = fmaxf(rm[s], fmaxf(S[b][n0][2 * h], S[b][n0][2 * h + 1]));
            }
        }
        float corr[4];
#pragma unroll
        for (int s = 0; s < 4; s++) {
            rm[s] = fmaxf(rm[s], __shfl_xor_sync(0xffffffffu, rm[s], 1));
            rm[s] = fmaxf(rm[s], __shfl_xor_sync(0xffffffffu, rm[s], 2));
            float mn = fmaxf(mv[s], rm[s]);
            corr[s] = __expf(mv[s] - mn);
            mv[s] = mn;
        }
        float ls[4] = {0.f, 0.f, 0.f, 0.f};
#pragma unroll
        for (int n0 = 0; n0 < 8; n0++) {
            int chp = 4 * ((2 * n0 + (c4 >> 1)) ^ g) + ((2 * c4) & 3);
#pragma unroll
            for (int s = 0; s < 4; s++) {
                int b = s >> 1, h = s & 1;
                float p0 = __expf(S[b][n0][2 * h]     - mv[s]);
                float p1 = __expf(S[b][n0][2 * h + 1] - mv[s]);
                ls[s] += p0 + p1;
                int row = wm * 32 + b * 16 + h * 8 + g;
                *(uint2*)(Ps + row * 64 + chp) = make_uint2(f2tf(p0), f2tf(p1));
            }
        }
#pragma unroll
        for (int s = 0; s < 4; s++) {
            ls[s] += __shfl_xor_sync(0xffffffffu, ls[s], 1);
            ls[s] += __shfl_xor_sync(0xffffffffu, ls[s], 2);
            lv[s] = lv[s] * corr[s] + ls[s];
            int b = s >> 1, h = s & 1;
#pragma unroll
            for (int n0 = 0; n0 < 8; n0++) {
                O[b][n0][2 * h]     *= corr[s];
                O[b][n0][2 * h + 1] *= corr[s];
            }
        }
        __syncwarp();

#pragma unroll
        for (int k0 = 0; k0 < 8; k0++) {
            int ch0 = 4 * ((2 * k0) ^ g);
            int ch1 = 4 * ((2 * k0 + 1) ^ g);
            uint32_t a[2][4];
#pragma unroll
            for (int b = 0; b < 2; b++) {
                int rL = (wm * 32 + b * 16 + g) * 64;
                a[b][0] = Ps[rL + ch0 + c4];
                a[b][1] = Ps[rL + 512 + ch0 + c4];
                a[b][2] = Ps[rL + ch1 + c4];
                a[b][3] = Ps[rL + 512 + ch1 + c4];
            }
            int ky0 = (k0 * 8 + c4) * 64;
            int ky1 = ky0 + 256;
            int sw = 2 * c4;
#pragma unroll
            for (int n0 = 0; n0 < 8; n0++) {
                int ch = 4 * ((2 * n0 + (g >> 2)) ^ sw) + (g & 3);
                uint32_t b0 = Vs[ky0 + ch];
                uint32_t b1 = Vs[ky1 + ch];
                mma_tf32(O[0][n0], a[0][0], a[0][1], a[0][2], a[0][3], b0, b1);
                mma_tf32(O[1][n0], a[1][0], a[1][1], a[1][2], a[1][3], b0, b1);
            }
        }
    }

    float* Op = g_Opart[sp];
#pragma unroll
    for (int b = 0; b < 2; b++) {
        int rowA = qBase + wm * 32 + b * 16 + g;
#pragma unroll
        for (int n0 = 0; n0 < 8; n0++) {
            int col = n0 * 8 + 2 * c4;
            *(float2*)(Op + rowA * 64 + col)       = make_float2(O[b][n0][0], O[b][n0][1]);
            *(float2*)(Op + (rowA + 8) * 64 + col) = make_float2(O[b][n0][2], O[b][n0][3]);
        }
    }
    if (c4 == 0) {
#pragma unroll
        for (int s = 0; s < 4; s++) {
            int row = qBase + wm * 32 + (s >> 1) * 16 + (s & 1) * 8 + g;
            g_mpart[sp][row] = mv[s];
            g_lpart[sp][row] = lv[s];
        }
    }
}

// ============================================================
// Kernel 3: combine split-K partials.
// ============================================================
__global__ __launch_bounds__(256) void cs_combine_kernel(float* __restrict__ outX)
{
    int gidx = blockIdx.x * 256 + threadIdx.x;
    int row = gidx >> 4;
    int e4 = gidx & 15;
    if (row >= N_ROWS) return;

    float m[NSPLIT];
    float M = -3.4e38f;
#pragma unroll
    for (int s = 0; s < NSPLIT; s++) { m[s] = g_mpart[s][row]; M = fmaxf(M, m[s]); }
    float wgt[NSPLIT];
    float denom = 0.f;
#pragma unroll
    for (int s = 0; s < NSPLIT; s++) {
        wgt[s] = __expf(m[s] - M);
        denom += wgt[s] * g_lpart[s][row];
    }
    float inv = 1.f / denom;

    float4 o = {0.f, 0.f, 0.f, 0.f};
#pragma unroll
    for (int s = 0; s < NSPLIT; s++) {
        float4 a = ((const float4*)g_Opart[s])[row * 16 + e4];
        o.x = fmaf(a.x, wgt[s], o.x);
        o.y = fmaf(a.y, wgt[s], o.y);
        o.z = fmaf(a.z, wgt[s], o.z);
        o.w = fmaf(a.w, wgt[s], o.w);
    }
    o.x *= inv; o.y *= inv; o.z *= inv; o.w *= inv;
    ((float4*)outX)[row * 16 + e4] = o;
}

// ============================================================
extern "C" void kernel_launch(void* const* d_in, const int* in_sizes, int n_in,
                              void* d_out, int out_size)
{
    const float* x    = (const float*)d_in[0];
    const float* cb   = (const float*)d_in[1];
    const float* Wqis = (const float*)d_in[2];  const float* bqis = (const float*)d_in[3];
    const float* Wkis = (const float*)d_in[4];  const float* bkis = (const float*)d_in[5];
    const float* Wvis = (const float*)d_in[6];  const float* bvis = (const float*)d_in[7];
    const float* Wqcs = (const float*)d_in[8];  const float* bqcs = (const float*)d_in[9];
    const float* Wkcs = (const float*)d_in[10]; const float* bkcs = (const float*)d_in[11];
    const float* Wvcs = (const float*)d_in[12]; const float* bvcs = (const float*)d_in[13];
    float* out = (float*)d_out;

    cudaFuncSetAttribute(attn_kernel,
                         cudaFuncAttributeMaxDynamicSharedMemorySize, 98304);

    proj_kernel<<<600, 256>>>(x, Wqis, bqis, Wkis, bkis, Wvis, bvis,
                              Wqcs, bqcs, Wkcs, bkcs, Wvcs, bvcs);
    attn_kernel<<<528, 128, 98304>>>(x, cb, out);
    cs_combine_kernel<<<(N_ROWS * 16 + 255) / 256, 256>>>(out + 2 * N_ROWS * DIMV);
}